// round 3
// baseline (speedup 1.0000x reference)
#include <cuda_runtime.h>
#include <cuda_bf16.h>
#include <math.h>

#define HIDDEN 768
#define HEADS  12
#define DK     64
#define BATCH  8
#define SEQ    512
#define ORDERS 3
#define NEGV   -1e9f

// ---------------- scratch (device globals; no allocs allowed) ----------------
__device__ float g_qh[BATCH * HEADS * SEQ * DK];     // [b][h][n][d], pre-scaled by 1/8
__device__ float g_kh[BATCH * HEADS * SEQ * DK];
__device__ float g_vh[BATCH * HEADS * SEQ * DK];
__device__ float g_atted[BATCH * SEQ * HIDDEN];      // [b*512+n][h*64+d]
__device__ float g_pooled[BATCH * HIDDEN];
__device__ float g_alphas[BATCH * ORDERS];
__device__ int   g_mask_mode;                        // 0=uint8, 1=int32, 2=float32

// ---------------- mask dtype detection (runs on device, graph-safe) ---------
__global__ void detect_mask_mode(const unsigned* __restrict__ m) {
    __shared__ int sflags;
    if (threadIdx.x == 0) sflags = 0;
    __syncthreads();
    int local = 0;
    for (int i = threadIdx.x; i < 16384; i += 256) {
        unsigned w = m[i];
        if (w == 0x3F800000u) local |= 1;          // float32 1.0f
        else if (w != 0u && w != 1u) local |= 2;   // packed uint8 bytes
    }
    if (local) atomicOr(&sflags, local);
    __syncthreads();
    if (threadIdx.x == 0)
        g_mask_mode = (sflags & 1) ? 2 : ((sflags & 2) ? 0 : 1);
}

// ---------------- routing kernel 1: masked attention pooling ----------------
__global__ __launch_bounds__(256) void route_pool(const float* __restrict__ v,
                                                  const float* __restrict__ pool_w,
                                                  const float* __restrict__ pool_b) {
    int b = blockIdx.x;
    int tid = threadIdx.x, warp = tid >> 5, lane = tid & 31;
    __shared__ float sc[SEQ];
    __shared__ float red[8], red2[8];
    __shared__ float pw[HIDDEN];
    for (int d = tid; d < HIDDEN; d += 256) pw[d] = pool_w[d];
    __syncthreads();

    // scores: one warp per row n
    for (int n = warp; n < SEQ; n += 8) {
        const float* vp = v + ((size_t)b * SEQ + n) * HIDDEN;
        float dot = 0.f, asum = 0.f;
        for (int d = lane; d < HIDDEN; d += 32) {
            float x = vp[d];
            dot += x * pw[d];
            asum += fabsf(x);
        }
        #pragma unroll
        for (int o = 16; o; o >>= 1) {
            dot  += __shfl_xor_sync(0xffffffffu, dot, o);
            asum += __shfl_xor_sync(0xffffffffu, asum, o);
        }
        if (lane == 0) sc[n] = (asum == 0.f) ? NEGV : (dot + pool_b[0]);
    }
    __syncthreads();

    // softmax over 512
    float m = fmaxf(sc[tid], sc[tid + 256]);
    #pragma unroll
    for (int o = 16; o; o >>= 1) m = fmaxf(m, __shfl_xor_sync(0xffffffffu, m, o));
    if (lane == 0) red[warp] = m;
    __syncthreads();
    if (tid == 0) {
        float t = red[0];
        #pragma unroll
        for (int i = 1; i < 8; i++) t = fmaxf(t, red[i]);
        red[0] = t;
    }
    __syncthreads();
    m = red[0];
    float e0 = __expf(sc[tid] - m), e1 = __expf(sc[tid + 256] - m);
    float s = e0 + e1;
    #pragma unroll
    for (int o = 16; o; o >>= 1) s += __shfl_xor_sync(0xffffffffu, s, o);
    if (lane == 0) red2[warp] = s;
    __syncthreads();
    if (tid == 0) {
        float t = 0.f;
        #pragma unroll
        for (int i = 0; i < 8; i++) t += red2[i];
        red2[0] = t;
    }
    __syncthreads();
    float inv = 1.f / red2[0];
    sc[tid] = e0 * inv;
    sc[tid + 256] = e1 * inv;
    __syncthreads();

    // pooled[d] = sum_n v[b,n,d] * p[n]   (coalesced over d)
    float a0 = 0.f, a1 = 0.f, a2 = 0.f;
    for (int n = 0; n < SEQ; n++) {
        float p = sc[n];
        const float* vp = v + ((size_t)b * SEQ + n) * HIDDEN;
        a0 += vp[tid]       * p;
        a1 += vp[tid + 256] * p;
        a2 += vp[tid + 512] * p;
    }
    g_pooled[b * HIDDEN + tid]       = a0;
    g_pooled[b * HIDDEN + tid + 256] = a1;
    g_pooled[b * HIDDEN + tid + 512] = a2;
}

// ---------------- routing kernel 2: MLP + softmax -> alphas ----------------
__global__ __launch_bounds__(384) void route_mlp(const float* __restrict__ w1,
                                                 const float* __restrict__ w2,
                                                 const float* __restrict__ b2) {
    int b = blockIdx.x, tid = threadIdx.x;
    __shared__ float pl[HIDDEN];
    __shared__ float pred[12 * 3];
    for (int d = tid; d < HIDDEN; d += 384) pl[d] = g_pooled[b * HIDDEN + d];
    __syncthreads();
    float acc = 0.f;
    for (int k = 0; k < HIDDEN; k++) acc += pl[k] * w1[k * 384 + tid];
    float hv = fmaxf(acc, 0.f);
    float p0 = hv * w2[tid * 3 + 0];
    float p1 = hv * w2[tid * 3 + 1];
    float p2 = hv * w2[tid * 3 + 2];
    #pragma unroll
    for (int o = 16; o; o >>= 1) {
        p0 += __shfl_xor_sync(0xffffffffu, p0, o);
        p1 += __shfl_xor_sync(0xffffffffu, p1, o);
        p2 += __shfl_xor_sync(0xffffffffu, p2, o);
    }
    int warp = tid >> 5;
    if ((tid & 31) == 0) { pred[warp * 3] = p0; pred[warp * 3 + 1] = p1; pred[warp * 3 + 2] = p2; }
    __syncthreads();
    if (tid == 0) {
        float l0 = b2[0], l1 = b2[1], l2 = b2[2];
        for (int w = 0; w < 12; w++) { l0 += pred[w * 3]; l1 += pred[w * 3 + 1]; l2 += pred[w * 3 + 2]; }
        float mm = fmaxf(l0, fmaxf(l1, l2));
        float e0 = __expf(l0 - mm), e1 = __expf(l1 - mm), e2 = __expf(l2 - mm);
        float z = e0 + e1 + e2;
        g_alphas[b * 3 + 0] = e0 / z;
        g_alphas[b * 3 + 1] = e1 / z;
        g_alphas[b * 3 + 2] = e2 / z;
    }
}

// ---------------- 64x64 tiled fp32 GEMM, C = (X W + bias) * scale -----------
// headlayout=1: out[((b*12+h)*512+n)*64+d]  (row i=b*512+n, col j=h*64+d)
// headlayout=0: out[i*Ncols + j]
__global__ __launch_bounds__(256) void gemm64(const float* __restrict__ X,
                                              const float* __restrict__ W,
                                              const float* __restrict__ bias,
                                              float* __restrict__ out,
                                              int Kdim, int Ncols,
                                              float scale, int headlayout) {
    __shared__ float Xs[16][64];   // [k][row]  (transposed)
    __shared__ float Ws[16][64];   // [k][col]
    int tid = threadIdx.x;
    int bn = blockIdx.x, bm = blockIdx.y;
    int tr = tid >> 4, tc = tid & 15;
    int row0 = bm * 64, col0 = bn * 64;
    int lxr = tid >> 2;            // 0..63
    int lxk = (tid & 3) * 4;       // 0,4,8,12
    int lwk = tid >> 4;            // 0..15
    int lwc = (tid & 15) * 4;      // 0..60

    float acc[4][4] = {};
    for (int kt = 0; kt < Kdim; kt += 16) {
        float4 xv = *(const float4*)(X + (size_t)(row0 + lxr) * Kdim + kt + lxk);
        float4 wv = *(const float4*)(W + (size_t)(kt + lwk) * Ncols + col0 + lwc);
        __syncthreads();
        Xs[lxk + 0][lxr] = xv.x;
        Xs[lxk + 1][lxr] = xv.y;
        Xs[lxk + 2][lxr] = xv.z;
        Xs[lxk + 3][lxr] = xv.w;
        *(float4*)&Ws[lwk][lwc] = wv;
        __syncthreads();
        #pragma unroll
        for (int kk = 0; kk < 16; kk++) {
            float4 a4 = *(const float4*)&Xs[kk][tr * 4];
            float4 b4 = *(const float4*)&Ws[kk][tc * 4];
            float av[4] = {a4.x, a4.y, a4.z, a4.w};
            float bv[4] = {b4.x, b4.y, b4.z, b4.w};
            #pragma unroll
            for (int i = 0; i < 4; i++)
                #pragma unroll
                for (int j = 0; j < 4; j++)
                    acc[i][j] += av[i] * bv[j];
        }
    }
    // epilogue
    int gj0 = col0 + tc * 4;
    float4 bb = *(const float4*)(bias + gj0);
    float bvv[4] = {bb.x, bb.y, bb.z, bb.w};
    #pragma unroll
    for (int i = 0; i < 4; i++) {
        int gi = row0 + tr * 4 + i;
        float4 o4;
        o4.x = (acc[i][0] + bvv[0]) * scale;
        o4.y = (acc[i][1] + bvv[1]) * scale;
        o4.z = (acc[i][2] + bvv[2]) * scale;
        o4.w = (acc[i][3] + bvv[3]) * scale;
        if (headlayout) {
            int b = gi >> 9, n = gi & 511;
            int h = gj0 >> 6, d = gj0 & 63;
            *(float4*)&out[(((size_t)b * HEADS + h) * SEQ + n) * DK + d] = o4;
        } else {
            *(float4*)&out[(size_t)gi * Ncols + gj0] = o4;
        }
    }
}

// ---------------- fused attention: scores, 3 masked softmaxes, mix, A@V -----
#define SPITCH 516
#define QKPITCH 68
#define ATTN_SMEM ((64 * SPITCH + 64 * QKPITCH + 64 * QKPITCH) * 4 + 64 * 48 * 4 + 16)

__global__ __launch_bounds__(256) void attn_kernel(const void* __restrict__ masks) {
    extern __shared__ float sm[];
    float* S   = sm;                         // 64 x 516
    float* Qt  = S + 64 * SPITCH;            // transposed [d][r], pitch 68
    float* KVt = Qt + 64 * QKPITCH;          // K transposed / V natural
    unsigned* mw = (unsigned*)(KVt + 64 * QKPITCH);  // 64 x 48 packed mask bits
    float* salpha = (float*)(mw + 64 * 48);

    int rt = blockIdx.x, h = blockIdx.y, b = blockIdx.z;
    int tid = threadIdx.x;
    int tr = tid >> 4, tc = tid & 15;
    int mode = g_mask_mode;

    const float* Qg = g_qh + (((size_t)(b * HEADS + h)) * SEQ + rt * 64) * DK;
    const float* Kg = g_kh + ((size_t)(b * HEADS + h)) * SEQ * DK;
    const float* Vg = g_vh + ((size_t)(b * HEADS + h)) * SEQ * DK;

    if (tid < 3) salpha[tid] = g_alphas[b * 3 + tid];
    for (int idx = tid; idx < 4096; idx += 256) {
        int r = idx >> 6, d = idx & 63;
        Qt[d * QKPITCH + r] = Qg[idx];
    }

    // ---- phase 1: S[64][512] = Q K^T (q pre-scaled by 1/8) ----
    for (int mt = 0; mt < 8; mt++) {
        __syncthreads();
        for (int idx = tid; idx < 4096; idx += 256) {
            int r = idx >> 6, d = idx & 63;
            KVt[d * QKPITCH + r] = Kg[mt * 4096 + idx];
        }
        __syncthreads();
        float a[4][4] = {};
        #pragma unroll 16
        for (int kk = 0; kk < 64; kk++) {
            float4 q4 = *(const float4*)&Qt[kk * QKPITCH + tr * 4];
            float4 k4 = *(const float4*)&KVt[kk * QKPITCH + tc * 4];
            float qa[4] = {q4.x, q4.y, q4.z, q4.w};
            float ka[4] = {k4.x, k4.y, k4.z, k4.w};
            #pragma unroll
            for (int i = 0; i < 4; i++)
                #pragma unroll
                for (int j = 0; j < 4; j++)
                    a[i][j] += qa[i] * ka[j];
        }
        #pragma unroll
        for (int i = 0; i < 4; i++)
            *(float4*)&S[(tr * 4 + i) * SPITCH + mt * 64 + tc * 4] =
                make_float4(a[i][0], a[i][1], a[i][2], a[i][3]);
    }
    __syncthreads();

    // ---- phase 2: per-row: E = exp(s - rowmax); Z_l over !mask_l; combine ----
    int warp = tid >> 5, lane = tid & 31;
    const unsigned char* m8 = (const unsigned char*)masks;
    const int*           mi = (const int*)masks;
    const float*         mf = (const float*)masks;
    for (int r = warp * 8; r < warp * 8 + 8; r++) {
        float* Sr = S + r * SPITCH;
        int n = rt * 64 + r;
        size_t off0 = ((size_t)(0 * BATCH + b) * SEQ + n) * SEQ;
        size_t off1 = ((size_t)(1 * BATCH + b) * SEQ + n) * SEQ;
        size_t off2 = ((size_t)(2 * BATCH + b) * SEQ + n) * SEQ;

        float mx = -1e30f;
        #pragma unroll
        for (int it = 0; it < 16; it++) mx = fmaxf(mx, Sr[it * 32 + lane]);
        #pragma unroll
        for (int o = 16; o; o >>= 1) mx = fmaxf(mx, __shfl_xor_sync(0xffffffffu, mx, o));

        float z0 = 0.f, z1 = 0.f, z2 = 0.f;
        #pragma unroll
        for (int it = 0; it < 16; it++) {
            int c = it * 32 + lane;
            float e = __expf(Sr[c] - mx);
            Sr[c] = e;
            bool b0, b1, b2;
            if (mode == 1) {
                b0 = mi[off0 + c] != 0;  b1 = mi[off1 + c] != 0;  b2 = mi[off2 + c] != 0;
            } else if (mode == 2) {
                b0 = mf[off0 + c] != 0.f; b1 = mf[off1 + c] != 0.f; b2 = mf[off2 + c] != 0.f;
            } else {
                b0 = m8[off0 + c] != 0;  b1 = m8[off1 + c] != 0;  b2 = m8[off2 + c] != 0;
            }
            unsigned w0 = __ballot_sync(0xffffffffu, b0);
            unsigned w1 = __ballot_sync(0xffffffffu, b1);
            unsigned w2 = __ballot_sync(0xffffffffu, b2);
            if (!b0) z0 += e;
            if (!b1) z1 += e;
            if (!b2) z2 += e;
            if (lane == 0) {
                mw[r * 48 + it * 3 + 0] = w0;
                mw[r * 48 + it * 3 + 1] = w1;
                mw[r * 48 + it * 3 + 2] = w2;
            }
        }
        #pragma unroll
        for (int o = 16; o; o >>= 1) {
            z0 += __shfl_xor_sync(0xffffffffu, z0, o);
            z1 += __shfl_xor_sync(0xffffffffu, z1, o);
            z2 += __shfl_xor_sync(0xffffffffu, z2, o);
        }
        __syncwarp();
        float wa0 = salpha[0] / z0, wa1 = salpha[1] / z1, wa2 = salpha[2] / z2;
        #pragma unroll
        for (int it = 0; it < 16; it++) {
            int c = it * 32 + lane;
            unsigned w0 = mw[r * 48 + it * 3 + 0];
            unsigned w1 = mw[r * 48 + it * 3 + 1];
            unsigned w2 = mw[r * 48 + it * 3 + 2];
            float coef = (((w0 >> lane) & 1) ? 0.f : wa0)
                       + (((w1 >> lane) & 1) ? 0.f : wa1)
                       + (((w2 >> lane) & 1) ? 0.f : wa2);
            Sr[c] *= coef;
        }
    }

    // ---- phase 3: O[64][64] = A[64][512] @ V[512][64] ----
    float* Vs = KVt;  // natural layout, pitch 64
    float o[4][4] = {};
    for (int mt = 0; mt < 8; mt++) {
        __syncthreads();
        const float4* src = (const float4*)(Vg + mt * 4096);
        float4* dst = (float4*)Vs;
        for (int idx = tid; idx < 1024; idx += 256) dst[idx] = src[idx];
        __syncthreads();
        #pragma unroll 8
        for (int mm = 0; mm < 64; mm++) {
            float a0 = S[(tr * 4 + 0) * SPITCH + mt * 64 + mm];
            float a1 = S[(tr * 4 + 1) * SPITCH + mt * 64 + mm];
            float a2 = S[(tr * 4 + 2) * SPITCH + mt * 64 + mm];
            float a3 = S[(tr * 4 + 3) * SPITCH + mt * 64 + mm];
            float4 v4 = *(const float4*)&Vs[mm * 64 + tc * 4];
            float vv[4] = {v4.x, v4.y, v4.z, v4.w};
            float aa[4] = {a0, a1, a2, a3};
            #pragma unroll
            for (int i = 0; i < 4; i++)
                #pragma unroll
                for (int j = 0; j < 4; j++)
                    o[i][j] += aa[i] * vv[j];
        }
    }
    // atted layout: [b*512+n][h*64+d]
    #pragma unroll
    for (int i = 0; i < 4; i++) {
        int row = tr * 4 + i;
        size_t off = ((size_t)(b * SEQ + rt * 64 + row) * HEADS + h) * DK + tc * 4;
        *(float4*)&g_atted[off] = make_float4(o[i][0], o[i][1], o[i][2], o[i][3]);
    }
}

// ---------------- launch ----------------
extern "C" void kernel_launch(void* const* d_in, const int* in_sizes, int n_in,
                              void* d_out, int out_size) {
    const float* v = (const float*)d_in[0];
    const float* k = (const float*)d_in[1];
    const float* q = (const float*)d_in[2];
    const void*  masks = d_in[3];
    // d_in[4]=tau, d_in[5]=training : unused by inference path
    const float* Wv = (const float*)d_in[6];
    const float* bv = (const float*)d_in[7];
    const float* Wk = (const float*)d_in[8];
    const float* bk = (const float*)d_in[9];
    const float* Wq = (const float*)d_in[10];
    const float* bq = (const float*)d_in[11];
    const float* Wm = (const float*)d_in[12];
    const float* bm = (const float*)d_in[13];
    const float* pool_w = (const float*)d_in[14];
    const float* pool_b = (const float*)d_in[15];
    const float* w1 = (const float*)d_in[16];
    const float* w2 = (const float*)d_in[17];
    const float* b2 = (const float*)d_in[18];
    float* out = (float*)d_out;

    float *qh, *kh, *vh, *atted;
    cudaGetSymbolAddress((void**)&qh, g_qh);
    cudaGetSymbolAddress((void**)&kh, g_kh);
    cudaGetSymbolAddress((void**)&vh, g_vh);
    cudaGetSymbolAddress((void**)&atted, g_atted);

    cudaFuncSetAttribute(attn_kernel, cudaFuncAttributeMaxDynamicSharedMemorySize, ATTN_SMEM);

    detect_mask_mode<<<1, 256>>>((const unsigned*)masks);
    route_pool<<<BATCH, 256>>>(v, pool_w, pool_b);
    route_mlp<<<BATCH, 384>>>(w1, w2, b2);

    dim3 gg(HIDDEN / 64, (BATCH * SEQ) / 64);  // (12, 64)
    gemm64<<<gg, 256>>>(q, Wq, bq, qh, HIDDEN, HIDDEN, 0.125f, 1);
    gemm64<<<gg, 256>>>(k, Wk, bk, kh, HIDDEN, HIDDEN, 1.f, 1);
    gemm64<<<gg, 256>>>(v, Wv, bv, vh, HIDDEN, HIDDEN, 1.f, 1);

    attn_kernel<<<dim3(SEQ / 64, HEADS, BATCH), 256, ATTN_SMEM>>>(masks);

    gemm64<<<gg, 256>>>(atted, Wm, bm, out, HIDDEN, HIDDEN, 1.f, 0);
}

// round 6
// speedup vs baseline: 1.2858x; 1.2858x over previous
#include <cuda_runtime.h>
#include <cuda_bf16.h>
#include <math.h>

#define HIDDEN 768
#define HEADS  12
#define DK     64
#define BATCH  8
#define SEQ    512
#define ORDERS 3
#define NEGV   -1e9f
typedef unsigned long long ull;

__device__ float g_qh[BATCH * HEADS * SEQ * DK];
__device__ float g_kh[BATCH * HEADS * SEQ * DK];
__device__ float g_vh[BATCH * HEADS * SEQ * DK];
__device__ float g_atted[BATCH * SEQ * HIDDEN];
__device__ float g_pooled[BATCH * HIDDEN];
__device__ float g_alphas[BATCH * ORDERS];
__device__ int   g_mask_mode;
__device__ unsigned g_packed[ORDERS * BATCH * SEQ * 16];

// ---- f32x2 helpers ----
__device__ __forceinline__ ull bc2(float x) {
    ull r; asm("mov.b64 %0, {%1, %1};" : "=l"(r) : "f"(x)); return r;
}
__device__ __forceinline__ void ffma2(ull& d, ull a, ull b) {
    asm("fma.rn.f32x2 %0, %1, %2, %0;" : "+l"(d) : "l"(a), "l"(b));
}
__device__ __forceinline__ float2 upk2(ull v) {
    float2 f; asm("mov.b64 {%0, %1}, %2;" : "=f"(f.x), "=f"(f.y) : "l"(v)); return f;
}

// ---- mask dtype detection ----
__global__ void detect_mask_mode(const unsigned* __restrict__ m) {
    __shared__ int sflags;
    if (threadIdx.x == 0) sflags = 0;
    __syncthreads();
    int local = 0;
    for (int i = threadIdx.x; i < 16384; i += 256) {
        unsigned w = m[i];
        if (w == 0x3F800000u) local |= 1;
        else if (w != 0u && w != 1u) local |= 2;
    }
    if (local) atomicOr(&sflags, local);
    __syncthreads();
    if (threadIdx.x == 0)
        g_mask_mode = (sflags & 1) ? 2 : ((sflags & 2) ? 0 : 1);
}

// ---- pack masks to bits: g_packed[row*16+w], row = (lev*8+b)*512+n ----
__global__ __launch_bounds__(256) void pack_masks(const void* __restrict__ masks) {
    int mode = g_mask_mode;
    int warp = threadIdx.x >> 5, lane = threadIdx.x & 31;
    int row = blockIdx.x * 8 + warp;
    size_t base = (size_t)row * SEQ;
    #pragma unroll 4
    for (int w16 = 0; w16 < 16; w16++) {
        int c = w16 * 32 + lane;
        bool bit;
        if (mode == 1)      bit = ((const int*)masks)[base + c] != 0;
        else if (mode == 2) bit = ((const float*)masks)[base + c] != 0.f;
        else                bit = ((const unsigned char*)masks)[base + c] != 0;
        unsigned bal = __ballot_sync(0xffffffffu, bit);
        if (lane == 0) g_packed[row * 16 + w16] = bal;
    }
}

// ---- routing 1: masked attention pooling ----
__global__ __launch_bounds__(256) void route_pool(const float* __restrict__ v,
                                                  const float* __restrict__ pool_w,
                                                  const float* __restrict__ pool_b) {
    int b = blockIdx.x;
    int tid = threadIdx.x, warp = tid >> 5, lane = tid & 31;
    __shared__ float sc[SEQ];
    __shared__ float red[8], red2[8];
    __shared__ float pw[HIDDEN];
    for (int d = tid; d < HIDDEN; d += 256) pw[d] = pool_w[d];
    __syncthreads();
    for (int n = warp; n < SEQ; n += 8) {
        const float* vp = v + ((size_t)b * SEQ + n) * HIDDEN;
        float dot = 0.f, asum = 0.f;
        for (int d = lane; d < HIDDEN; d += 32) {
            float x = vp[d];
            dot += x * pw[d];
            asum += fabsf(x);
        }
        #pragma unroll
        for (int o = 16; o; o >>= 1) {
            dot  += __shfl_xor_sync(0xffffffffu, dot, o);
            asum += __shfl_xor_sync(0xffffffffu, asum, o);
        }
        if (lane == 0) sc[n] = (asum == 0.f) ? NEGV : (dot + pool_b[0]);
    }
    __syncthreads();
    float m = fmaxf(sc[tid], sc[tid + 256]);
    #pragma unroll
    for (int o = 16; o; o >>= 1) m = fmaxf(m, __shfl_xor_sync(0xffffffffu, m, o));
    if (lane == 0) red[warp] = m;
    __syncthreads();
    if (tid == 0) {
        float t = red[0];
        for (int i = 1; i < 8; i++) t = fmaxf(t, red[i]);
        red[0] = t;
    }
    __syncthreads();
    m = red[0];
    float e0 = __expf(sc[tid] - m), e1 = __expf(sc[tid + 256] - m);
    float s = e0 + e1;
    #pragma unroll
    for (int o = 16; o; o >>= 1) s += __shfl_xor_sync(0xffffffffu, s, o);
    if (lane == 0) red2[warp] = s;
    __syncthreads();
    if (tid == 0) {
        float t = 0.f;
        for (int i = 0; i < 8; i++) t += red2[i];
        red2[0] = t;
    }
    __syncthreads();
    float inv = 1.f / red2[0];
    sc[tid] = e0 * inv;
    sc[tid + 256] = e1 * inv;
    __syncthreads();
    float a0 = 0.f, a1 = 0.f, a2 = 0.f;
    for (int n = 0; n < SEQ; n++) {
        float p = sc[n];
        const float* vp = v + ((size_t)b * SEQ + n) * HIDDEN;
        a0 += vp[tid] * p;
        a1 += vp[tid + 256] * p;
        a2 += vp[tid + 512] * p;
    }
    g_pooled[b * HIDDEN + tid]       = a0;
    g_pooled[b * HIDDEN + tid + 256] = a1;
    g_pooled[b * HIDDEN + tid + 512] = a2;
}

// ---- routing 2: MLP + softmax ----
__global__ __launch_bounds__(384) void route_mlp(const float* __restrict__ w1,
                                                 const float* __restrict__ w2,
                                                 const float* __restrict__ b2) {
    int b = blockIdx.x, tid = threadIdx.x;
    __shared__ float pl[HIDDEN];
    __shared__ float pred[12 * 3];
    for (int d = tid; d < HIDDEN; d += 384) pl[d] = g_pooled[b * HIDDEN + d];
    __syncthreads();
    float acc = 0.f;
    for (int k = 0; k < HIDDEN; k++) acc += pl[k] * w1[k * 384 + tid];
    float hv = fmaxf(acc, 0.f);
    float p0 = hv * w2[tid * 3 + 0];
    float p1 = hv * w2[tid * 3 + 1];
    float p2 = hv * w2[tid * 3 + 2];
    #pragma unroll
    for (int o = 16; o; o >>= 1) {
        p0 += __shfl_xor_sync(0xffffffffu, p0, o);
        p1 += __shfl_xor_sync(0xffffffffu, p1, o);
        p2 += __shfl_xor_sync(0xffffffffu, p2, o);
    }
    int warp = tid >> 5;
    if ((tid & 31) == 0) { pred[warp*3] = p0; pred[warp*3+1] = p1; pred[warp*3+2] = p2; }
    __syncthreads();
    if (tid == 0) {
        float l0 = b2[0], l1 = b2[1], l2 = b2[2];
        for (int w = 0; w < 12; w++) { l0 += pred[w*3]; l1 += pred[w*3+1]; l2 += pred[w*3+2]; }
        float mm = fmaxf(l0, fmaxf(l1, l2));
        float e0 = __expf(l0 - mm), e1 = __expf(l1 - mm), e2 = __expf(l2 - mm);
        float z = e0 + e1 + e2;
        g_alphas[b*3+0] = e0 / z; g_alphas[b*3+1] = e1 / z; g_alphas[b*3+2] = e2 / z;
    }
}

// ---- FFMA2 GEMM: 128x64 tile, 128 threads, 8x8 microtile ----
__global__ __launch_bounds__(128) void gemm_f2(const float* __restrict__ X,
                                               const float* __restrict__ W,
                                               const float* __restrict__ bias,
                                               float* __restrict__ out,
                                               float scale, int headlayout) {
    __shared__ float Xs[16][132];
    __shared__ float Ws[16][68];
    int tid = threadIdx.x;
    int row0 = blockIdx.y * 128, col0 = blockIdx.x * 64;
    int r0 = (tid >> 3) * 8;
    int c0 = (tid & 7) * 8;

    ull acc[8][4];
    #pragma unroll
    for (int i = 0; i < 8; i++)
        #pragma unroll
        for (int j = 0; j < 4; j++) acc[i][j] = 0ull;

    for (int kt = 0; kt < 768; kt += 16) {
        __syncthreads();
        {
            const float* xp = X + (size_t)(row0 + tid) * 768 + kt;
            #pragma unroll
            for (int q = 0; q < 4; q++) {
                float4 xv = *(const float4*)(xp + q * 4);
                Xs[q*4+0][tid] = xv.x; Xs[q*4+1][tid] = xv.y;
                Xs[q*4+2][tid] = xv.z; Xs[q*4+3][tid] = xv.w;
            }
        }
        #pragma unroll
        for (int it = 0; it < 2; it++) {
            int e = tid + it * 128;
            int k = e >> 4, c4 = (e & 15) * 4;
            *(float4*)&Ws[k][c4] = *(const float4*)&W[(size_t)(kt + k) * 768 + col0 + c4];
        }
        __syncthreads();
        #pragma unroll
        for (int kk = 0; kk < 16; kk++) {
            float4 a0 = *(const float4*)&Xs[kk][r0];
            float4 a1 = *(const float4*)&Xs[kk][r0 + 4];
            ulonglong2 b01 = *(const ulonglong2*)&Ws[kk][c0];
            ulonglong2 b23 = *(const ulonglong2*)&Ws[kk][c0 + 4];
            float aa[8] = {a0.x, a0.y, a0.z, a0.w, a1.x, a1.y, a1.z, a1.w};
            #pragma unroll
            for (int i = 0; i < 8; i++) {
                ull A = bc2(aa[i]);
                ffma2(acc[i][0], A, b01.x);
                ffma2(acc[i][1], A, b01.y);
                ffma2(acc[i][2], A, b23.x);
                ffma2(acc[i][3], A, b23.y);
            }
        }
    }
    int gj = col0 + c0;
    float4 bb0 = *(const float4*)&bias[gj];
    float4 bb1 = *(const float4*)&bias[gj + 4];
    #pragma unroll
    for (int i = 0; i < 8; i++) {
        int gi = row0 + r0 + i;
        float2 u0 = upk2(acc[i][0]), u1 = upk2(acc[i][1]);
        float2 u2 = upk2(acc[i][2]), u3 = upk2(acc[i][3]);
        float4 o0 = make_float4((u0.x+bb0.x)*scale, (u0.y+bb0.y)*scale,
                                (u1.x+bb0.z)*scale, (u1.y+bb0.w)*scale);
        float4 o1 = make_float4((u2.x+bb1.x)*scale, (u2.y+bb1.y)*scale,
                                (u3.x+bb1.z)*scale, (u3.y+bb1.w)*scale);
        if (headlayout) {
            int b = gi >> 9, n = gi & 511;
            int h = gj >> 6, d = gj & 63;
            size_t off = (((size_t)b * HEADS + h) * SEQ + n) * DK + d;
            *(float4*)&out[off] = o0;
            *(float4*)&out[off + 4] = o1;
        } else {
            *(float4*)&out[(size_t)gi * 768 + gj] = o0;
            *(float4*)&out[(size_t)gi * 768 + gj + 4] = o1;
        }
    }
}

// ---- fused attention ----
#define SPITCH 516
#define QKPITCH 68
#define ATTN_SMEM ((64 * SPITCH + 2 * 64 * QKPITCH) * 4)

__global__ __launch_bounds__(256) void attn_kernel() {
    extern __shared__ float sm[];
    float* S   = sm;                       // 64 x 516
    float* Qt  = S + 64 * SPITCH;          // [d][r] pitch 68
    float* KVt = Qt + 64 * QKPITCH;        // K transposed / V natural

    int rt = blockIdx.x, h = blockIdx.y, b = blockIdx.z;
    int tid = threadIdx.x;
    int tr = tid >> 4, tc = tid & 15;

    const float* Qg = g_qh + (((size_t)(b * HEADS + h)) * SEQ + rt * 64) * DK;
    const float* Kg = g_kh + ((size_t)(b * HEADS + h)) * SEQ * DK;
    const float* Vg = g_vh + ((size_t)(b * HEADS + h)) * SEQ * DK;

    for (int idx = tid; idx < 4096; idx += 256) {
        int r = idx >> 6, d = idx & 63;
        Qt[d * QKPITCH + r] = Qg[idx];
    }

    // phase 1: S = Q K^T  (q pre-scaled)
    for (int mt = 0; mt < 8; mt++) {
        __syncthreads();
        for (int idx = tid; idx < 4096; idx += 256) {
            int r = idx >> 6, d = idx & 63;
            KVt[d * QKPITCH + r] = Kg[mt * 4096 + idx];
        }
        __syncthreads();
        ull a2[4][2];
        #pragma unroll
        for (int i = 0; i < 4; i++) { a2[i][0] = 0ull; a2[i][1] = 0ull; }
        #pragma unroll 16
        for (int kk = 0; kk < 64; kk++) {
            float4 q4 = *(const float4*)&Qt[kk * QKPITCH + tr * 4];
            ulonglong2 kb = *(const ulonglong2*)&KVt[kk * QKPITCH + tc * 4];
            float qa[4] = {q4.x, q4.y, q4.z, q4.w};
            #pragma unroll
            for (int i = 0; i < 4; i++) {
                ull A = bc2(qa[i]);
                ffma2(a2[i][0], A, kb.x);
                ffma2(a2[i][1], A, kb.y);
            }
        }
        #pragma unroll
        for (int i = 0; i < 4; i++) {
            float2 u0 = upk2(a2[i][0]), u1 = upk2(a2[i][1]);
            *(float4*)&S[(tr*4+i) * SPITCH + mt*64 + tc*4] =
                make_float4(u0.x, u0.y, u1.x, u1.y);
        }
    }
    __syncthreads();

    // phase 2: E = exp(s - rowmax); Z_l over !mask_l; combine with alphas
    int warp = tid >> 5, lane = tid & 31;
    float wa0g = __ldg(&g_alphas[b*3+0]);
    float wa1g = __ldg(&g_alphas[b*3+1]);
    float wa2g = __ldg(&g_alphas[b*3+2]);
    for (int r = warp; r < 64; r += 8) {
        float* Sr = S + r * SPITCH;
        int n = rt * 64 + r;
        const unsigned* p0 = g_packed + ((size_t)(0*BATCH + b) * SEQ + n) * 16;
        const unsigned* p1 = g_packed + ((size_t)(1*BATCH + b) * SEQ + n) * 16;
        const unsigned* p2 = g_packed + ((size_t)(2*BATCH + b) * SEQ + n) * 16;

        float mx = -1e30f;
        #pragma unroll
        for (int it = 0; it < 16; it++) mx = fmaxf(mx, Sr[it * 32 + lane]);
        #pragma unroll
        for (int o = 16; o; o >>= 1) mx = fmaxf(mx, __shfl_xor_sync(0xffffffffu, mx, o));

        float z0 = 0.f, z1 = 0.f, z2 = 0.f;
        #pragma unroll
        for (int it = 0; it < 16; it++) {
            int c = it * 32 + lane;
            float e = __expf(Sr[c] - mx);
            Sr[c] = e;
            unsigned w0 = __ldg(p0 + it), w1 = __ldg(p1 + it), w2 = __ldg(p2 + it);
            if (!((w0 >> lane) & 1)) z0 += e;
            if (!((w1 >> lane) & 1)) z1 += e;
            if (!((w2 >> lane) & 1)) z2 += e;
        }
        #pragma unroll
        for (int o = 16; o; o >>= 1) {
            z0 += __shfl_xor_sync(0xffffffffu, z0, o);
            z1 += __shfl_xor_sync(0xffffffffu, z1, o);
            z2 += __shfl_xor_sync(0xffffffffu, z2, o);
        }
        float wa0 = wa0g / z0, wa1 = wa1g / z1, wa2 = wa2g / z2;
        #pragma unroll
        for (int it = 0; it < 16; it++) {
            int c = it * 32 + lane;
            unsigned w0 = __ldg(p0 + it), w1 = __ldg(p1 + it), w2 = __ldg(p2 + it);
            float coef = (((w0 >> lane) & 1) ? 0.f : wa0)
                       + (((w1 >> lane) & 1) ? 0.f : wa1)
                       + (((w2 >> lane) & 1) ? 0.f : wa2);
            Sr[c] *= coef;
        }
    }

    // phase 3: O = A @ V
    float* Vs = KVt;
    ull o2[4][2];
    #pragma unroll
    for (int i = 0; i < 4; i++) { o2[i][0] = 0ull; o2[i][1] = 0ull; }
    for (int mt = 0; mt < 8; mt++) {
        __syncthreads();
        const float4* src = (const float4*)(Vg + mt * 4096);
        float4* dst = (float4*)Vs;
        #pragma unroll
        for (int it = 0; it < 4; it++) dst[tid + it * 256] = src[tid + it * 256];
        __syncthreads();
        #pragma unroll 8
        for (int mm = 0; mm < 64; mm++) {
            float a0 = S[(tr*4+0) * SPITCH + mt*64 + mm];
            float a1 = S[(tr*4+1) * SPITCH + mt*64 + mm];
            float a2 = S[(tr*4+2) * SPITCH + mt*64 + mm];
            float a3 = S[(tr*4+3) * SPITCH + mt*64 + mm];
            ulonglong2 vb = *(const ulonglong2*)&Vs[mm * 64 + tc * 4];
            float aa[4] = {a0, a1, a2, a3};
            #pragma unroll
            for (int i = 0; i < 4; i++) {
                ull A = bc2(aa[i]);
                ffma2(o2[i][0], A, vb.x);
                ffma2(o2[i][1], A, vb.y);
            }
        }
    }
    #pragma unroll
    for (int i = 0; i < 4; i++) {
        float2 u0 = upk2(o2[i][0]), u1 = upk2(o2[i][1]);
        size_t off = ((size_t)(b * SEQ + rt * 64 + tr * 4 + i) * HEADS + h) * DK + tc * 4;
        *(float4*)&g_atted[off] = make_float4(u0.x, u0.y, u1.x, u1.y);
    }
}

// ---- launch ----
extern "C" void kernel_launch(void* const* d_in, const int* in_sizes, int n_in,
                              void* d_out, int out_size) {
    const float* v = (const float*)d_in[0];
    const float* k = (const float*)d_in[1];
    const float* q = (const float*)d_in[2];
    const void*  masks = d_in[3];
    const float* Wv = (const float*)d_in[6];
    const float* bv = (const float*)d_in[7];
    const float* Wk = (const float*)d_in[8];
    const float* bk = (const float*)d_in[9];
    const float* Wq = (const float*)d_in[10];
    const float* bq = (const float*)d_in[11];
    const float* Wm = (const float*)d_in[12];
    const float* bm = (const float*)d_in[13];
    const float* pool_w = (const float*)d_in[14];
    const float* pool_b = (const float*)d_in[15];
    const float* w1 = (const float*)d_in[16];
    const float* w2 = (const float*)d_in[17];
    const float* b2 = (const float*)d_in[18];
    float* out = (float*)d_out;

    float *qh, *kh, *vh, *atted;
    cudaGetSymbolAddress((void**)&qh, g_qh);
    cudaGetSymbolAddress((void**)&kh, g_kh);
    cudaGetSymbolAddress((void**)&vh, g_vh);
    cudaGetSymbolAddress((void**)&atted, g_atted);

    cudaFuncSetAttribute(attn_kernel, cudaFuncAttributeMaxDynamicSharedMemorySize, ATTN_SMEM);

    detect_mask_mode<<<1, 256>>>((const unsigned*)masks);
    pack_masks<<<ORDERS * BATCH * SEQ / 8, 256>>>(masks);
    route_pool<<<BATCH, 256>>>(v, pool_w, pool_b);
    route_mlp<<<BATCH, 384>>>(w1, w2, b2);

    dim3 gg(HIDDEN / 64, (BATCH * SEQ) / 128);  // (12, 32)
    gemm_f2<<<gg, 128>>>(q, Wq, bq, qh, 0.125f, 1);
    gemm_f2<<<gg, 128>>>(k, Wk, bk, kh, 1.f, 1);
    gemm_f2<<<gg, 128>>>(v, Wv, bv, vh, 1.f, 1);

    attn_kernel<<<dim3(SEQ / 64, HEADS, BATCH), 256, ATTN_SMEM>>>();

    gemm_f2<<<gg, 128>>>(atted, Wm, bm, out, 1.f, 0);
}

// round 7
// speedup vs baseline: 1.7735x; 1.3793x over previous
#include <cuda_runtime.h>
#include <cuda_bf16.h>
#include <math.h>

#define HIDDEN 768
#define HEADS  12
#define DK     64
#define BATCH  8
#define SEQ    512
#define ORDERS 3
#define NEGV   -1e9f
typedef unsigned long long ull;

__device__ float g_qh[BATCH * HEADS * SEQ * DK];
__device__ float g_kh[BATCH * HEADS * SEQ * DK];
__device__ float g_vh[BATCH * HEADS * SEQ * DK];
__device__ float g_atted[BATCH * SEQ * HIDDEN];
__device__ float g_pooled[BATCH * HIDDEN];
__device__ float g_alphas[BATCH * ORDERS];
__device__ int   g_mask_mode;
__device__ unsigned g_packed[ORDERS * BATCH * SEQ * 16];

// ---- f32x2 helpers ----
__device__ __forceinline__ ull bc2(float x) {
    ull r; asm("mov.b64 %0, {%1, %1};" : "=l"(r) : "f"(x)); return r;
}
__device__ __forceinline__ void ffma2(ull& d, ull a, ull b) {
    asm("fma.rn.f32x2 %0, %1, %2, %0;" : "+l"(d) : "l"(a), "l"(b));
}
__device__ __forceinline__ float2 upk2(ull v) {
    float2 f; asm("mov.b64 {%0, %1}, %2;" : "=f"(f.x), "=f"(f.y) : "l"(v)); return f;
}

// ---- mask dtype detection ----
__global__ void detect_mask_mode(const unsigned* __restrict__ m) {
    __shared__ int sflags;
    if (threadIdx.x == 0) sflags = 0;
    __syncthreads();
    int local = 0;
    for (int i = threadIdx.x; i < 16384; i += 256) {
        unsigned w = m[i];
        if (w == 0x3F800000u) local |= 1;
        else if (w != 0u && w != 1u) local |= 2;
    }
    if (local) atomicOr(&sflags, local);
    __syncthreads();
    if (threadIdx.x == 0)
        g_mask_mode = (sflags & 1) ? 2 : ((sflags & 2) ? 0 : 1);
}

// ---- pack masks to bits ----
__global__ __launch_bounds__(256) void pack_masks(const void* __restrict__ masks) {
    int mode = g_mask_mode;
    int warp = threadIdx.x >> 5, lane = threadIdx.x & 31;
    int row = blockIdx.x * 8 + warp;
    size_t base = (size_t)row * SEQ;
    #pragma unroll 4
    for (int w16 = 0; w16 < 16; w16++) {
        int c = w16 * 32 + lane;
        bool bit;
        if (mode == 1)      bit = ((const int*)masks)[base + c] != 0;
        else if (mode == 2) bit = ((const float*)masks)[base + c] != 0.f;
        else                bit = ((const unsigned char*)masks)[base + c] != 0;
        unsigned bal = __ballot_sync(0xffffffffu, bit);
        if (lane == 0) g_packed[row * 16 + w16] = bal;
    }
}

// ---- routing 1: masked attention pooling ----
__global__ __launch_bounds__(256) void route_pool(const float* __restrict__ v,
                                                  const float* __restrict__ pool_w,
                                                  const float* __restrict__ pool_b) {
    int b = blockIdx.x;
    int tid = threadIdx.x, warp = tid >> 5, lane = tid & 31;
    __shared__ float sc[SEQ];
    __shared__ float red[8], red2[8];
    __shared__ float pw[HIDDEN];
    for (int d = tid; d < HIDDEN; d += 256) pw[d] = pool_w[d];
    __syncthreads();
    for (int n = warp; n < SEQ; n += 8) {
        const float* vp = v + ((size_t)b * SEQ + n) * HIDDEN;
        float dot = 0.f, asum = 0.f;
        #pragma unroll 4
        for (int d = lane; d < HIDDEN; d += 32) {
            float x = vp[d];
            dot += x * pw[d];
            asum += fabsf(x);
        }
        #pragma unroll
        for (int o = 16; o; o >>= 1) {
            dot  += __shfl_xor_sync(0xffffffffu, dot, o);
            asum += __shfl_xor_sync(0xffffffffu, asum, o);
        }
        if (lane == 0) sc[n] = (asum == 0.f) ? NEGV : (dot + pool_b[0]);
    }
    __syncthreads();
    float m = fmaxf(sc[tid], sc[tid + 256]);
    #pragma unroll
    for (int o = 16; o; o >>= 1) m = fmaxf(m, __shfl_xor_sync(0xffffffffu, m, o));
    if (lane == 0) red[warp] = m;
    __syncthreads();
    if (tid == 0) {
        float t = red[0];
        for (int i = 1; i < 8; i++) t = fmaxf(t, red[i]);
        red[0] = t;
    }
    __syncthreads();
    m = red[0];
    float e0 = __expf(sc[tid] - m), e1 = __expf(sc[tid + 256] - m);
    float s = e0 + e1;
    #pragma unroll
    for (int o = 16; o; o >>= 1) s += __shfl_xor_sync(0xffffffffu, s, o);
    if (lane == 0) red2[warp] = s;
    __syncthreads();
    if (tid == 0) {
        float t = 0.f;
        for (int i = 0; i < 8; i++) t += red2[i];
        red2[0] = t;
    }
    __syncthreads();
    float inv = 1.f / red2[0];
    sc[tid] = e0 * inv;
    sc[tid + 256] = e1 * inv;
    __syncthreads();
    float a0 = 0.f, a1 = 0.f, a2 = 0.f;
    #pragma unroll 4
    for (int n = 0; n < SEQ; n++) {
        float p = sc[n];
        const float* vp = v + ((size_t)b * SEQ + n) * HIDDEN;
        a0 += vp[tid] * p;
        a1 += vp[tid + 256] * p;
        a2 += vp[tid + 512] * p;
    }
    g_pooled[b * HIDDEN + tid]       = a0;
    g_pooled[b * HIDDEN + tid + 256] = a1;
    g_pooled[b * HIDDEN + tid + 512] = a2;
}

// ---- routing 2: MLP + softmax ----
__global__ __launch_bounds__(384) void route_mlp(const float* __restrict__ w1,
                                                 const float* __restrict__ w2,
                                                 const float* __restrict__ b2) {
    int b = blockIdx.x, tid = threadIdx.x;
    __shared__ float pl[HIDDEN];
    __shared__ float pred[12 * 3];
    for (int d = tid; d < HIDDEN; d += 384) pl[d] = g_pooled[b * HIDDEN + d];
    __syncthreads();
    float acc = 0.f;
    #pragma unroll 16
    for (int k = 0; k < HIDDEN; k++) acc += pl[k] * __ldg(&w1[k * 384 + tid]);
    float hv = fmaxf(acc, 0.f);
    float p0 = hv * w2[tid * 3 + 0];
    float p1 = hv * w2[tid * 3 + 1];
    float p2 = hv * w2[tid * 3 + 2];
    #pragma unroll
    for (int o = 16; o; o >>= 1) {
        p0 += __shfl_xor_sync(0xffffffffu, p0, o);
        p1 += __shfl_xor_sync(0xffffffffu, p1, o);
        p2 += __shfl_xor_sync(0xffffffffu, p2, o);
    }
    int warp = tid >> 5;
    if ((tid & 31) == 0) { pred[warp*3] = p0; pred[warp*3+1] = p1; pred[warp*3+2] = p2; }
    __syncthreads();
    if (tid == 0) {
        float l0 = b2[0], l1 = b2[1], l2 = b2[2];
        for (int w = 0; w < 12; w++) { l0 += pred[w*3]; l1 += pred[w*3+1]; l2 += pred[w*3+2]; }
        float mm = fmaxf(l0, fmaxf(l1, l2));
        float e0 = __expf(l0 - mm), e1 = __expf(l1 - mm), e2 = __expf(l2 - mm);
        float z = e0 + e1 + e2;
        g_alphas[b*3+0] = e0 / z; g_alphas[b*3+1] = e1 / z; g_alphas[b*3+2] = e2 / z;
    }
}

// ---- FFMA2 GEMM core (128x64 tile, 128 threads, 8x8 microtile) ----
__device__ __forceinline__ void gemm_body(const float* __restrict__ X,
                                          const float* __restrict__ W,
                                          const float* __restrict__ bias,
                                          float* __restrict__ out,
                                          float scale, int headlayout,
                                          int row0, int col0) {
    __shared__ float Xs[16][132];
    __shared__ float Ws[16][68];
    int tid = threadIdx.x;
    int r0 = (tid >> 3) * 8;
    int c0 = (tid & 7) * 8;

    ull acc[8][4];
    #pragma unroll
    for (int i = 0; i < 8; i++)
        #pragma unroll
        for (int j = 0; j < 4; j++) acc[i][j] = 0ull;

    for (int kt = 0; kt < 768; kt += 16) {
        __syncthreads();
        {
            const float* xp = X + (size_t)(row0 + tid) * 768 + kt;
            #pragma unroll
            for (int q = 0; q < 4; q++) {
                float4 xv = *(const float4*)(xp + q * 4);
                Xs[q*4+0][tid] = xv.x; Xs[q*4+1][tid] = xv.y;
                Xs[q*4+2][tid] = xv.z; Xs[q*4+3][tid] = xv.w;
            }
        }
        #pragma unroll
        for (int it = 0; it < 2; it++) {
            int e = tid + it * 128;
            int k = e >> 4, c4 = (e & 15) * 4;
            *(float4*)&Ws[k][c4] = *(const float4*)&W[(size_t)(kt + k) * 768 + col0 + c4];
        }
        __syncthreads();
        #pragma unroll
        for (int kk = 0; kk < 16; kk++) {
            float4 a0 = *(const float4*)&Xs[kk][r0];
            float4 a1 = *(const float4*)&Xs[kk][r0 + 4];
            ulonglong2 b01 = *(const ulonglong2*)&Ws[kk][c0];
            ulonglong2 b23 = *(const ulonglong2*)&Ws[kk][c0 + 4];
            float aa[8] = {a0.x, a0.y, a0.z, a0.w, a1.x, a1.y, a1.z, a1.w};
            #pragma unroll
            for (int i = 0; i < 8; i++) {
                ull A = bc2(aa[i]);
                ffma2(acc[i][0], A, b01.x);
                ffma2(acc[i][1], A, b01.y);
                ffma2(acc[i][2], A, b23.x);
                ffma2(acc[i][3], A, b23.y);
            }
        }
    }
    int gj = col0 + c0;
    float4 bb0 = *(const float4*)&bias[gj];
    float4 bb1 = *(const float4*)&bias[gj + 4];
    #pragma unroll
    for (int i = 0; i < 8; i++) {
        int gi = row0 + r0 + i;
        float2 u0 = upk2(acc[i][0]), u1 = upk2(acc[i][1]);
        float2 u2 = upk2(acc[i][2]), u3 = upk2(acc[i][3]);
        float4 o0 = make_float4((u0.x+bb0.x)*scale, (u0.y+bb0.y)*scale,
                                (u1.x+bb0.z)*scale, (u1.y+bb0.w)*scale);
        float4 o1 = make_float4((u2.x+bb1.x)*scale, (u2.y+bb1.y)*scale,
                                (u3.x+bb1.z)*scale, (u3.y+bb1.w)*scale);
        if (headlayout) {
            int b = gi >> 9, n = gi & 511;
            int h = gj >> 6, d = gj & 63;
            size_t off = (((size_t)b * HEADS + h) * SEQ + n) * DK + d;
            *(float4*)&out[off] = o0;
            *(float4*)&out[off + 4] = o1;
        } else {
            *(float4*)&out[(size_t)gi * 768 + gj] = o0;
            *(float4*)&out[(size_t)gi * 768 + gj + 4] = o1;
        }
    }
}

// fused QKV: blockIdx.z selects {q,k,v}
__global__ __launch_bounds__(128) void gemm_qkv(const float* __restrict__ q,
                                                const float* __restrict__ k,
                                                const float* __restrict__ v,
                                                const float* __restrict__ Wq,
                                                const float* __restrict__ Wk,
                                                const float* __restrict__ Wv,
                                                const float* __restrict__ bq,
                                                const float* __restrict__ bk,
                                                const float* __restrict__ bv) {
    int z = blockIdx.z;
    const float *X, *W, *bias;
    float* out;
    float scale;
    if (z == 0)      { X = q; W = Wq; bias = bq; out = g_qh; scale = 0.125f; }
    else if (z == 1) { X = k; W = Wk; bias = bk; out = g_kh; scale = 1.f; }
    else             { X = v; W = Wv; bias = bv; out = g_vh; scale = 1.f; }
    gemm_body(X, W, bias, out, scale, 1, blockIdx.y * 128, blockIdx.x * 64);
}

__global__ __launch_bounds__(128) void gemm_out(const float* __restrict__ X,
                                                const float* __restrict__ W,
                                                const float* __restrict__ bias,
                                                float* __restrict__ out) {
    gemm_body(X, W, bias, out, 1.f, 0, blockIdx.y * 128, blockIdx.x * 64);
}

// ---- fused attention ----
#define SPITCH 516
#define QTP 68
#define KTP 132
#define ATTN_SMEM ((64 * SPITCH + 64 * QTP + 64 * KTP) * 4)

__global__ __launch_bounds__(256) void attn_kernel() {
    extern __shared__ float sm[];
    float* S   = sm;                       // [r][c] 64 x 516
    float* Qt  = S + 64 * SPITCH;          // [d][r] pitch 68 (scratch in phase 3)
    float* KVt = Qt + 64 * QTP;            // K^T [d][c] pitch 132 / V natural

    int rt = blockIdx.x, h = blockIdx.y, b = blockIdx.z;
    int tid = threadIdx.x;

    const float* Qg = g_qh + (((size_t)(b * HEADS + h)) * SEQ + rt * 64) * DK;
    const float* Kg = g_kh + ((size_t)(b * HEADS + h)) * SEQ * DK;
    const float* Vg = g_vh + ((size_t)(b * HEADS + h)) * SEQ * DK;

    // load Q transposed, conflict-free: gather 4 rows (stride-64 loads, coalesced
    // across d) and store float4 along r
    {
        int d = tid & 63, rg = tid >> 6;
        #pragma unroll
        for (int it = 0; it < 4; it++) {
            int r0 = (rg + it * 4) * 4;
            float4 qv = make_float4(Qg[(r0+0)*DK + d], Qg[(r0+1)*DK + d],
                                    Qg[(r0+2)*DK + d], Qg[(r0+3)*DK + d]);
            *(float4*)&Qt[d * QTP + r0] = qv;
        }
    }

    // ---- phase 1: S[r][c] = Q K^T over 4 chunks of 128 cols ----
    int tr = tid >> 4;          // 0..15 -> r0 = tr*4
    int tcg = tid & 15;         // 0..15 -> c0 = tcg*8
    int r0p = tr * 4, c0p = tcg * 8;
    for (int ch = 0; ch < 4; ch++) {
        __syncthreads();
        {
            int d = tid & 63, cg = tid >> 6;
            #pragma unroll
            for (int it = 0; it < 8; it++) {
                int c0 = (cg + it * 4) * 4;
                const float* kp = Kg + (ch * 128 + c0) * DK + d;
                float4 kv = make_float4(kp[0], kp[DK], kp[2*DK], kp[3*DK]);
                *(float4*)&KVt[d * KTP + c0] = kv;
            }
        }
        __syncthreads();
        ull acc[4][4];
        #pragma unroll
        for (int i = 0; i < 4; i++)
            #pragma unroll
            for (int j = 0; j < 4; j++) acc[i][j] = 0ull;
        #pragma unroll 8
        for (int kk = 0; kk < 64; kk++) {
            float4 q4 = *(const float4*)&Qt[kk * QTP + r0p];
            ulonglong2 b01 = *(const ulonglong2*)&KVt[kk * KTP + c0p];
            ulonglong2 b23 = *(const ulonglong2*)&KVt[kk * KTP + c0p + 4];
            float qa[4] = {q4.x, q4.y, q4.z, q4.w};
            #pragma unroll
            for (int i = 0; i < 4; i++) {
                ull A = bc2(qa[i]);
                ffma2(acc[i][0], A, b01.x);
                ffma2(acc[i][1], A, b01.y);
                ffma2(acc[i][2], A, b23.x);
                ffma2(acc[i][3], A, b23.y);
            }
        }
        #pragma unroll
        for (int i = 0; i < 4; i++) {
            float2 u0 = upk2(acc[i][0]), u1 = upk2(acc[i][1]);
            float2 u2 = upk2(acc[i][2]), u3 = upk2(acc[i][3]);
            float* dst = &S[(r0p + i) * SPITCH + ch * 128 + c0p];
            *(float4*)dst       = make_float4(u0.x, u0.y, u1.x, u1.y);
            *(float4*)(dst + 4) = make_float4(u2.x, u2.y, u3.x, u3.y);
        }
    }
    __syncthreads();

    // ---- phase 2 ----
    int warp = tid >> 5, lane = tid & 31;
    float wa0g = __ldg(&g_alphas[b*3+0]);
    float wa1g = __ldg(&g_alphas[b*3+1]);
    float wa2g = __ldg(&g_alphas[b*3+2]);
    for (int r = warp; r < 64; r += 8) {
        float* Sr = S + r * SPITCH;
        int n = rt * 64 + r;
        const unsigned* p0 = g_packed + ((size_t)(0*BATCH + b) * SEQ + n) * 16;
        const unsigned* p1 = g_packed + ((size_t)(1*BATCH + b) * SEQ + n) * 16;
        const unsigned* p2 = g_packed + ((size_t)(2*BATCH + b) * SEQ + n) * 16;

        float mx = -1e30f;
        #pragma unroll
        for (int it = 0; it < 16; it++) mx = fmaxf(mx, Sr[it * 32 + lane]);
        #pragma unroll
        for (int o = 16; o; o >>= 1) mx = fmaxf(mx, __shfl_xor_sync(0xffffffffu, mx, o));

        float z0 = 0.f, z1 = 0.f, z2 = 0.f;
        #pragma unroll
        for (int it = 0; it < 16; it++) {
            int c = it * 32 + lane;
            float e = __expf(Sr[c] - mx);
            Sr[c] = e;
            unsigned w0 = __ldg(p0 + it), w1 = __ldg(p1 + it), w2 = __ldg(p2 + it);
            if (!((w0 >> lane) & 1)) z0 += e;
            if (!((w1 >> lane) & 1)) z1 += e;
            if (!((w2 >> lane) & 1)) z2 += e;
        }
        #pragma unroll
        for (int o = 16; o; o >>= 1) {
            z0 += __shfl_xor_sync(0xffffffffu, z0, o);
            z1 += __shfl_xor_sync(0xffffffffu, z1, o);
            z2 += __shfl_xor_sync(0xffffffffu, z2, o);
        }
        float wa0 = wa0g / z0, wa1 = wa1g / z1, wa2 = wa2g / z2;
        #pragma unroll
        for (int it = 0; it < 16; it++) {
            int c = it * 32 + lane;
            unsigned w0 = __ldg(p0 + it), w1 = __ldg(p1 + it), w2 = __ldg(p2 + it);
            float coef = (((w0 >> lane) & 1) ? 0.f : wa0)
                       + (((w1 >> lane) & 1) ? 0.f : wa1)
                       + (((w2 >> lane) & 1) ? 0.f : wa2);
            Sr[c] *= coef;
        }
    }

    // ---- phase 3: O = A @ V, split-m over 2 groups of 128 threads ----
    int g   = tid >> 7;          // 0 or 1
    int lt  = tid & 127;
    int tr3 = lt >> 3;           // 0..15 -> r0 = tr3*4
    int tc3 = lt & 7;            // 0..7  -> c0 = tc3*8
    int r03 = tr3 * 4, c03 = tc3 * 8;
    ull acc3[4][4];
    #pragma unroll
    for (int i = 0; i < 4; i++)
        #pragma unroll
        for (int j = 0; j < 4; j++) acc3[i][j] = 0ull;

    float* Vbase = KVt + g * 4096;     // two 64x64 V tiles
    for (int vt = 0; vt < 4; vt++) {
        __syncthreads();
        {
            const float4* src = (const float4*)(Vg + (vt * 2 + g) * 64 * DK);
            float4* dst = (float4*)Vbase;
            #pragma unroll
            for (int it = 0; it < 8; it++) dst[lt + it * 128] = src[lt + it * 128];
        }
        __syncthreads();
        int mg0 = (vt * 2 + g) * 64;
        #pragma unroll 4
        for (int mm = 0; mm < 64; mm++) {
            int mg = mg0 + mm;
            float a0 = S[(r03+0) * SPITCH + mg];
            float a1 = S[(r03+1) * SPITCH + mg];
            float a2 = S[(r03+2) * SPITCH + mg];
            float a3 = S[(r03+3) * SPITCH + mg];
            ulonglong2 v01 = *(const ulonglong2*)&Vbase[mm * 64 + c03];
            ulonglong2 v23 = *(const ulonglong2*)&Vbase[mm * 64 + c03 + 4];
            float aa[4] = {a0, a1, a2, a3};
            #pragma unroll
            for (int i = 0; i < 4; i++) {
                ull A = bc2(aa[i]);
                ffma2(acc3[i][0], A, v01.x);
                ffma2(acc3[i][1], A, v01.y);
                ffma2(acc3[i][2], A, v23.x);
                ffma2(acc3[i][3], A, v23.y);
            }
        }
    }
    __syncthreads();
    float* Sc = Qt;   // 64x64 scratch for group-1 partial
    if (g == 1) {
        #pragma unroll
        for (int i = 0; i < 4; i++) {
            float2 u0 = upk2(acc3[i][0]), u1 = upk2(acc3[i][1]);
            float2 u2 = upk2(acc3[i][2]), u3 = upk2(acc3[i][3]);
            float* dst = &Sc[(r03 + i) * 64 + c03];
            *(float4*)dst       = make_float4(u0.x, u0.y, u1.x, u1.y);
            *(float4*)(dst + 4) = make_float4(u2.x, u2.y, u3.x, u3.y);
        }
    }
    __syncthreads();
    if (g == 0) {
        #pragma unroll
        for (int i = 0; i < 4; i++) {
            float2 u0 = upk2(acc3[i][0]), u1 = upk2(acc3[i][1]);
            float2 u2 = upk2(acc3[i][2]), u3 = upk2(acc3[i][3]);
            const float* pp = &Sc[(r03 + i) * 64 + c03];
            float4 p0 = *(const float4*)pp;
            float4 p1 = *(const float4*)(pp + 4);
            size_t off = ((size_t)(b * SEQ + rt * 64 + r03 + i) * HEADS + h) * DK + c03;
            *(float4*)&g_atted[off] =
                make_float4(u0.x + p0.x, u0.y + p0.y, u1.x + p0.z, u1.y + p0.w);
            *(float4*)&g_atted[off + 4] =
                make_float4(u2.x + p1.x, u2.y + p1.y, u3.x + p1.z, u3.y + p1.w);
        }
    }
}

// ---- launch ----
extern "C" void kernel_launch(void* const* d_in, const int* in_sizes, int n_in,
                              void* d_out, int out_size) {
    const float* v = (const float*)d_in[0];
    const float* k = (const float*)d_in[1];
    const float* q = (const float*)d_in[2];
    const void*  masks = d_in[3];
    const float* Wv = (const float*)d_in[6];
    const float* bv = (const float*)d_in[7];
    const float* Wk = (const float*)d_in[8];
    const float* bk = (const float*)d_in[9];
    const float* Wq = (const float*)d_in[10];
    const float* bq = (const float*)d_in[11];
    const float* Wm = (const float*)d_in[12];
    const float* bm = (const float*)d_in[13];
    const float* pool_w = (const float*)d_in[14];
    const float* pool_b = (const float*)d_in[15];
    const float* w1 = (const float*)d_in[16];
    const float* w2 = (const float*)d_in[17];
    const float* b2 = (const float*)d_in[18];
    float* out = (float*)d_out;

    float* atted;
    cudaGetSymbolAddress((void**)&atted, g_atted);

    static cudaStream_t s1 = 0, s2 = 0;
    static cudaEvent_t evR = 0, ev1 = 0, ev2 = 0;
    if (!s1) {
        cudaStreamCreateWithFlags(&s1, cudaStreamNonBlocking);
        cudaStreamCreateWithFlags(&s2, cudaStreamNonBlocking);
        cudaEventCreateWithFlags(&evR, cudaEventDisableTiming);
        cudaEventCreateWithFlags(&ev1, cudaEventDisableTiming);
        cudaEventCreateWithFlags(&ev2, cudaEventDisableTiming);
        cudaFuncSetAttribute(attn_kernel, cudaFuncAttributeMaxDynamicSharedMemorySize, ATTN_SMEM);
    }

    // fork: routing branch (s1) + mask branch (s2) run concurrently with QKV GEMM
    cudaEventRecord(evR, 0);
    cudaStreamWaitEvent(s1, evR, 0);
    cudaStreamWaitEvent(s2, evR, 0);

    route_pool<<<BATCH, 256, 0, s1>>>(v, pool_w, pool_b);
    route_mlp<<<BATCH, 384, 0, s1>>>(w1, w2, b2);
    cudaEventRecord(ev1, s1);

    detect_mask_mode<<<1, 256, 0, s2>>>((const unsigned*)masks);
    pack_masks<<<ORDERS * BATCH * SEQ / 8, 256, 0, s2>>>(masks);
    cudaEventRecord(ev2, s2);

    dim3 gq(HIDDEN / 64, (BATCH * SEQ) / 128, 3);   // (12, 32, 3)
    gemm_qkv<<<gq, 128>>>(q, k, v, Wq, Wk, Wv, bq, bk, bv);

    // join
    cudaStreamWaitEvent(0, ev1, 0);
    cudaStreamWaitEvent(0, ev2, 0);

    attn_kernel<<<dim3(SEQ / 64, HEADS, BATCH), 256, ATTN_SMEM>>>();

    dim3 gg(HIDDEN / 64, (BATCH * SEQ) / 128);      // (12, 32)
    gemm_out<<<gg, 128>>>(atted, Wm, bm, out);
}

// round 8
// speedup vs baseline: 2.3425x; 1.3209x over previous
#include <cuda_runtime.h>
#include <cuda_bf16.h>
#include <math.h>

#define HIDDEN 768
#define HEADS  12
#define DK     64
#define BATCH  8
#define SEQ    512
#define ORDERS 3
#define NEGV   -1e9f
#define K2     (768 * 768)
typedef unsigned long long ull;

__device__ float g_qh[BATCH * HEADS * SEQ * DK];
__device__ float g_kh[BATCH * HEADS * SEQ * DK];
__device__ float g_vh[BATCH * HEADS * SEQ * DK];
__device__ float g_pooled[BATCH * HIDDEN];
__device__ float g_alphas[BATCH * ORDERS];
__device__ int   g_mask_mode;
__device__ unsigned g_packed[ORDERS * BATCH * SEQ * 16];
// packed bf16 split (lo<<16 | hi) buffers
__device__ unsigned g_qbf[BATCH * SEQ * HIDDEN];
__device__ unsigned g_kbf[BATCH * SEQ * HIDDEN];
__device__ unsigned g_vbf[BATCH * SEQ * HIDDEN];
__device__ unsigned g_abf[BATCH * SEQ * HIDDEN];
__device__ unsigned g_wbf[4 * K2];

// ---- helpers ----
__device__ __forceinline__ ull bc2(float x) {
    ull r; asm("mov.b64 %0, {%1, %1};" : "=l"(r) : "f"(x)); return r;
}
__device__ __forceinline__ void ffma2(ull& d, ull a, ull b) {
    asm("fma.rn.f32x2 %0, %1, %2, %0;" : "+l"(d) : "l"(a), "l"(b));
}
__device__ __forceinline__ float2 upk2(ull v) {
    float2 f; asm("mov.b64 {%0, %1}, %2;" : "=f"(f.x), "=f"(f.y) : "l"(v)); return f;
}
__device__ __forceinline__ unsigned packbf(float x) {
    __nv_bfloat16 h = __float2bfloat16_rn(x);
    float hf = __bfloat162float(h);
    __nv_bfloat16 l = __float2bfloat16_rn(x - hf);
    return ((unsigned)__bfloat16_as_ushort(l) << 16) | (unsigned)__bfloat16_as_ushort(h);
}

#define LDSM4(R, addr) \
    asm volatile("ldmatrix.sync.aligned.m8n8.x4.shared.b16 {%0,%1,%2,%3}, [%4];" \
        : "=r"((R)[0]), "=r"((R)[1]), "=r"((R)[2]), "=r"((R)[3]) : "r"(addr))
#define LDSM4T(R, addr) \
    asm volatile("ldmatrix.sync.aligned.m8n8.x4.trans.shared.b16 {%0,%1,%2,%3}, [%4];" \
        : "=r"((R)[0]), "=r"((R)[1]), "=r"((R)[2]), "=r"((R)[3]) : "r"(addr))
#define MMABF(C, A, B0, B1) \
    asm volatile("mma.sync.aligned.m16n8k16.row.col.f32.bf16.bf16.f32 " \
        "{%0,%1,%2,%3},{%4,%5,%6,%7},{%8,%9},{%0,%1,%2,%3};" \
        : "+f"((C)[0]), "+f"((C)[1]), "+f"((C)[2]), "+f"((C)[3]) \
        : "r"((A)[0]), "r"((A)[1]), "r"((A)[2]), "r"((A)[3]), "r"(B0), "r"(B1))

// ---- conversion kernels ----
__global__ __launch_bounds__(256) void conv_x(const float* __restrict__ q,
                                              const float* __restrict__ k,
                                              const float* __restrict__ v) {
    int z = blockIdx.y;
    const float* src = (z == 0) ? q : (z == 1) ? k : v;
    unsigned* dst = (z == 0) ? g_qbf : (z == 1) ? g_kbf : g_vbf;
    size_t i = (size_t)blockIdx.x * 256 + threadIdx.x;
    float4 x = ((const float4*)src)[i];
    uint4 o = make_uint4(packbf(x.x), packbf(x.y), packbf(x.z), packbf(x.w));
    ((uint4*)dst)[i] = o;
}
__global__ __launch_bounds__(256) void conv_w(const float* __restrict__ wq,
                                              const float* __restrict__ wk,
                                              const float* __restrict__ wv,
                                              const float* __restrict__ wm) {
    int z = blockIdx.y;
    const float* src = (z == 0) ? wq : (z == 1) ? wk : (z == 2) ? wv : wm;
    unsigned* dst = g_wbf + (size_t)z * K2;
    size_t i = (size_t)blockIdx.x * 256 + threadIdx.x;
    float4 x = ((const float4*)src)[i];
    uint4 o = make_uint4(packbf(x.x), packbf(x.y), packbf(x.z), packbf(x.w));
    ((uint4*)dst)[i] = o;
}

// ---- mask dtype detection ----
__global__ void detect_mask_mode(const unsigned* __restrict__ m) {
    __shared__ int sflags;
    if (threadIdx.x == 0) sflags = 0;
    __syncthreads();
    int local = 0;
    for (int i = threadIdx.x; i < 16384; i += 256) {
        unsigned w = m[i];
        if (w == 0x3F800000u) local |= 1;
        else if (w != 0u && w != 1u) local |= 2;
    }
    if (local) atomicOr(&sflags, local);
    __syncthreads();
    if (threadIdx.x == 0)
        g_mask_mode = (sflags & 1) ? 2 : ((sflags & 2) ? 0 : 1);
}

// ---- pack masks to bits ----
__global__ __launch_bounds__(256) void pack_masks(const void* __restrict__ masks) {
    int mode = g_mask_mode;
    int warp = threadIdx.x >> 5, lane = threadIdx.x & 31;
    int row = blockIdx.x * 8 + warp;
    size_t base = (size_t)row * SEQ;
    #pragma unroll 4
    for (int w16 = 0; w16 < 16; w16++) {
        int c = w16 * 32 + lane;
        bool bit;
        if (mode == 1)      bit = ((const int*)masks)[base + c] != 0;
        else if (mode == 2) bit = ((const float*)masks)[base + c] != 0.f;
        else                bit = ((const unsigned char*)masks)[base + c] != 0;
        unsigned bal = __ballot_sync(0xffffffffu, bit);
        if (lane == 0) g_packed[row * 16 + w16] = bal;
    }
}

// ---- routing 1: masked attention pooling ----
__global__ __launch_bounds__(256) void route_pool(const float* __restrict__ v,
                                                  const float* __restrict__ pool_w,
                                                  const float* __restrict__ pool_b) {
    int b = blockIdx.x;
    int tid = threadIdx.x, warp = tid >> 5, lane = tid & 31;
    __shared__ float sc[SEQ];
    __shared__ float red[8], red2[8];
    __shared__ float pw[HIDDEN];
    for (int d = tid; d < HIDDEN; d += 256) pw[d] = pool_w[d];
    __syncthreads();
    for (int n = warp; n < SEQ; n += 8) {
        const float* vp = v + ((size_t)b * SEQ + n) * HIDDEN;
        float dot = 0.f, asum = 0.f;
        #pragma unroll 4
        for (int d = lane; d < HIDDEN; d += 32) {
            float x = vp[d];
            dot += x * pw[d];
            asum += fabsf(x);
        }
        #pragma unroll
        for (int o = 16; o; o >>= 1) {
            dot  += __shfl_xor_sync(0xffffffffu, dot, o);
            asum += __shfl_xor_sync(0xffffffffu, asum, o);
        }
        if (lane == 0) sc[n] = (asum == 0.f) ? NEGV : (dot + pool_b[0]);
    }
    __syncthreads();
    float m = fmaxf(sc[tid], sc[tid + 256]);
    #pragma unroll
    for (int o = 16; o; o >>= 1) m = fmaxf(m, __shfl_xor_sync(0xffffffffu, m, o));
    if (lane == 0) red[warp] = m;
    __syncthreads();
    if (tid == 0) {
        float t = red[0];
        for (int i = 1; i < 8; i++) t = fmaxf(t, red[i]);
        red[0] = t;
    }
    __syncthreads();
    m = red[0];
    float e0 = __expf(sc[tid] - m), e1 = __expf(sc[tid + 256] - m);
    float s = e0 + e1;
    #pragma unroll
    for (int o = 16; o; o >>= 1) s += __shfl_xor_sync(0xffffffffu, s, o);
    if (lane == 0) red2[warp] = s;
    __syncthreads();
    if (tid == 0) {
        float t = 0.f;
        for (int i = 0; i < 8; i++) t += red2[i];
        red2[0] = t;
    }
    __syncthreads();
    float inv = 1.f / red2[0];
    sc[tid] = e0 * inv;
    sc[tid + 256] = e1 * inv;
    __syncthreads();
    float a0 = 0.f, a1 = 0.f, a2 = 0.f;
    #pragma unroll 4
    for (int n = 0; n < SEQ; n++) {
        float p = sc[n];
        const float* vp = v + ((size_t)b * SEQ + n) * HIDDEN;
        a0 += vp[tid] * p;
        a1 += vp[tid + 256] * p;
        a2 += vp[tid + 512] * p;
    }
    g_pooled[b * HIDDEN + tid]       = a0;
    g_pooled[b * HIDDEN + tid + 256] = a1;
    g_pooled[b * HIDDEN + tid + 512] = a2;
}

// ---- routing 2: MLP + softmax ----
__global__ __launch_bounds__(384) void route_mlp(const float* __restrict__ w1,
                                                 const float* __restrict__ w2,
                                                 const float* __restrict__ b2) {
    int b = blockIdx.x, tid = threadIdx.x;
    __shared__ float pl[HIDDEN];
    __shared__ float pred[12 * 3];
    for (int d = tid; d < HIDDEN; d += 384) pl[d] = g_pooled[b * HIDDEN + d];
    __syncthreads();
    float acc = 0.f;
    #pragma unroll 16
    for (int k = 0; k < HIDDEN; k++) acc += pl[k] * __ldg(&w1[k * 384 + tid]);
    float hv = fmaxf(acc, 0.f);
    float p0 = hv * w2[tid * 3 + 0];
    float p1 = hv * w2[tid * 3 + 1];
    float p2 = hv * w2[tid * 3 + 2];
    #pragma unroll
    for (int o = 16; o; o >>= 1) {
        p0 += __shfl_xor_sync(0xffffffffu, p0, o);
        p1 += __shfl_xor_sync(0xffffffffu, p1, o);
        p2 += __shfl_xor_sync(0xffffffffu, p2, o);
    }
    int warp = tid >> 5;
    if ((tid & 31) == 0) { pred[warp*3] = p0; pred[warp*3+1] = p1; pred[warp*3+2] = p2; }
    __syncthreads();
    if (tid == 0) {
        float l0 = b2[0], l1 = b2[1], l2 = b2[2];
        for (int w = 0; w < 12; w++) { l0 += pred[w*3]; l1 += pred[w*3+1]; l2 += pred[w*3+2]; }
        float mm = fmaxf(l0, fmaxf(l1, l2));
        float e0 = __expf(l0 - mm), e1 = __expf(l1 - mm), e2 = __expf(l2 - mm);
        float z = e0 + e1 + e2;
        g_alphas[b*3+0] = e0 / z; g_alphas[b*3+1] = e1 / z; g_alphas[b*3+2] = e2 / z;
    }
}

// ---- bf16-split tensor-core GEMM: 128x128 tile, 256 threads ----
// D = Ah*Bh + Ah*Bl + Al*Bh; inputs packed (lo<<16|hi)
__device__ __forceinline__ void gemm_bf_body(const unsigned* __restrict__ Xp,
                                             const unsigned* __restrict__ Wp,
                                             const float* __restrict__ bias,
                                             float* __restrict__ out,
                                             float scale, int headlayout,
                                             int row0, int col0) {
    __shared__ __align__(16) __nv_bfloat16 Ah[128][40], Al[128][40];
    __shared__ __align__(16) __nv_bfloat16 Bh[32][136], Bl[32][136];
    int tid = threadIdx.x;
    int wid = tid >> 5, lane = tid & 31;
    int wm = wid & 1, wn = wid >> 1;   // warp tile 64x32

    float acc[4][4][4];
    #pragma unroll
    for (int i = 0; i < 4; i++)
        #pragma unroll
        for (int j = 0; j < 4; j++)
            #pragma unroll
            for (int c = 0; c < 4; c++) acc[i][j][c] = 0.f;

    unsigned aaddr_h[4], aaddr_l[4];
    #pragma unroll
    for (int mt = 0; mt < 4; mt++) {
        aaddr_h[mt] = (unsigned)__cvta_generic_to_shared(
            &Ah[wm * 64 + mt * 16 + (lane & 15)][(lane >> 4) << 3]);
        aaddr_l[mt] = (unsigned)__cvta_generic_to_shared(
            &Al[wm * 64 + mt * 16 + (lane & 15)][(lane >> 4) << 3]);
    }
    unsigned baddr_h[2], baddr_l[2];
    #pragma unroll
    for (int nb = 0; nb < 2; nb++) {
        int kr = (lane & 7) + (((lane >> 3) & 1) << 3);
        int nc = wn * 32 + nb * 16 + ((lane >> 4) << 3);
        baddr_h[nb] = (unsigned)__cvta_generic_to_shared(&Bh[kr][nc]);
        baddr_l[nb] = (unsigned)__cvta_generic_to_shared(&Bl[kr][nc]);
    }

    for (int kt = 0; kt < 768; kt += 32) {
        __syncthreads();
        #pragma unroll
        for (int i = 0; i < 4; i++) {
            int e = tid + i * 256;
            int r = e >> 3, k0 = (e & 7) * 4;
            uint4 x = *(const uint4*)&Xp[(size_t)(row0 + r) * 768 + kt + k0];
            *(unsigned*)&Ah[r][k0]     = __byte_perm(x.x, x.y, 0x5410);
            *(unsigned*)&Al[r][k0]     = __byte_perm(x.x, x.y, 0x7632);
            *(unsigned*)&Ah[r][k0 + 2] = __byte_perm(x.z, x.w, 0x5410);
            *(unsigned*)&Al[r][k0 + 2] = __byte_perm(x.z, x.w, 0x7632);
        }
        #pragma unroll
        for (int i = 0; i < 4; i++) {
            int e = tid + i * 256;
            int kk = e >> 5, n0 = (e & 31) * 4;
            uint4 x = *(const uint4*)&Wp[(size_t)(kt + kk) * 768 + col0 + n0];
            *(unsigned*)&Bh[kk][n0]     = __byte_perm(x.x, x.y, 0x5410);
            *(unsigned*)&Bl[kk][n0]     = __byte_perm(x.x, x.y, 0x7632);
            *(unsigned*)&Bh[kk][n0 + 2] = __byte_perm(x.z, x.w, 0x5410);
            *(unsigned*)&Bl[kk][n0 + 2] = __byte_perm(x.z, x.w, 0x7632);
        }
        __syncthreads();
        #pragma unroll
        for (int ks = 0; ks < 2; ks++) {
            unsigned koff = ks * 32;   // 16 bf16 = 32 bytes
            unsigned ah[4][4], al[4][4], bh[2][4], bl[2][4];
            #pragma unroll
            for (int mt = 0; mt < 4; mt++) {
                LDSM4(ah[mt], aaddr_h[mt] + koff);
                LDSM4(al[mt], aaddr_l[mt] + koff);
            }
            #pragma unroll
            for (int nb = 0; nb < 2; nb++) {
                LDSM4T(bh[nb], baddr_h[nb] + ks * 16 * 272);
                LDSM4T(bl[nb], baddr_l[nb] + ks * 16 * 272);
            }
            #pragma unroll
            for (int mt = 0; mt < 4; mt++)
                #pragma unroll
                for (int nt = 0; nt < 4; nt++) {
                    unsigned bh0 = bh[nt >> 1][(nt & 1) * 2];
                    unsigned bh1 = bh[nt >> 1][(nt & 1) * 2 + 1];
                    unsigned bl0 = bl[nt >> 1][(nt & 1) * 2];
                    unsigned bl1 = bl[nt >> 1][(nt & 1) * 2 + 1];
                    MMABF(acc[mt][nt], ah[mt], bh0, bh1);
                    MMABF(acc[mt][nt], ah[mt], bl0, bl1);
                    MMABF(acc[mt][nt], al[mt], bh0, bh1);
                }
        }
    }

    int rbase = row0 + wm * 64, cbase = col0 + wn * 32;
    #pragma unroll
    for (int mt = 0; mt < 4; mt++) {
        #pragma unroll
        for (int nt = 0; nt < 4; nt++) {
            int gj = cbase + nt * 8 + (lane & 3) * 2;
            float b0 = __ldg(&bias[gj]), b1 = __ldg(&bias[gj + 1]);
            int r_lo = rbase + mt * 16 + (lane >> 2);
            int r_hi = r_lo + 8;
            float2 v0 = make_float2((acc[mt][nt][0] + b0) * scale,
                                    (acc[mt][nt][1] + b1) * scale);
            float2 v1 = make_float2((acc[mt][nt][2] + b0) * scale,
                                    (acc[mt][nt][3] + b1) * scale);
            if (headlayout) {
                int bb0 = r_lo >> 9, n0 = r_lo & 511;
                int h = gj >> 6, d = gj & 63;
                *(float2*)&out[(((size_t)bb0 * HEADS + h) * SEQ + n0) * DK + d] = v0;
                int bb1 = r_hi >> 9, n1 = r_hi & 511;
                *(float2*)&out[(((size_t)bb1 * HEADS + h) * SEQ + n1) * DK + d] = v1;
            } else {
                *(float2*)&out[(size_t)r_lo * 768 + gj] = v0;
                *(float2*)&out[(size_t)r_hi * 768 + gj] = v1;
            }
        }
    }
}

__global__ __launch_bounds__(256) void gemm_qkv_bf(const float* __restrict__ bq,
                                                   const float* __restrict__ bk,
                                                   const float* __restrict__ bv) {
    int z = blockIdx.z;
    const unsigned* Xp; const unsigned* Wp; const float* bias; float* out; float scale;
    if (z == 0)      { Xp = g_qbf; Wp = g_wbf;          bias = bq; out = g_qh; scale = 0.125f; }
    else if (z == 1) { Xp = g_kbf; Wp = g_wbf + K2;     bias = bk; out = g_kh; scale = 1.f; }
    else             { Xp = g_vbf; Wp = g_wbf + 2 * K2; bias = bv; out = g_vh; scale = 1.f; }
    gemm_bf_body(Xp, Wp, bias, out, scale, 1, blockIdx.y * 128, blockIdx.x * 128);
}

__global__ __launch_bounds__(256) void gemm_out_bf(const float* __restrict__ bias,
                                                   float* __restrict__ out) {
    gemm_bf_body(g_abf, g_wbf + 3 * K2, bias, out, 1.f, 0,
                 blockIdx.y * 128, blockIdx.x * 128);
}

// ---- fused attention (FFMA2), epilogue packs bf16-split for out-GEMM ----
#define SPITCH 516
#define QTP 68
#define KTP 132
#define ATTN_SMEM ((64 * SPITCH + 64 * QTP + 64 * KTP) * 4)

__global__ __launch_bounds__(256) void attn_kernel() {
    extern __shared__ float sm[];
    float* S   = sm;
    float* Qt  = S + 64 * SPITCH;
    float* KVt = Qt + 64 * QTP;

    int rt = blockIdx.x, h = blockIdx.y, b = blockIdx.z;
    int tid = threadIdx.x;

    const float* Qg = g_qh + (((size_t)(b * HEADS + h)) * SEQ + rt * 64) * DK;
    const float* Kg = g_kh + ((size_t)(b * HEADS + h)) * SEQ * DK;
    const float* Vg = g_vh + ((size_t)(b * HEADS + h)) * SEQ * DK;

    {
        int d = tid & 63, rg = tid >> 6;
        #pragma unroll
        for (int it = 0; it < 4; it++) {
            int r0 = (rg + it * 4) * 4;
            float4 qv = make_float4(Qg[(r0+0)*DK + d], Qg[(r0+1)*DK + d],
                                    Qg[(r0+2)*DK + d], Qg[(r0+3)*DK + d]);
            *(float4*)&Qt[d * QTP + r0] = qv;
        }
    }

    int tr = tid >> 4, tcg = tid & 15;
    int r0p = tr * 4, c0p = tcg * 8;
    for (int ch = 0; ch < 4; ch++) {
        __syncthreads();
        {
            int d = tid & 63, cg = tid >> 6;
            #pragma unroll
            for (int it = 0; it < 8; it++) {
                int c0 = (cg + it * 4) * 4;
                const float* kp = Kg + (ch * 128 + c0) * DK + d;
                float4 kv = make_float4(kp[0], kp[DK], kp[2*DK], kp[3*DK]);
                *(float4*)&KVt[d * KTP + c0] = kv;
            }
        }
        __syncthreads();
        ull acc[4][4];
        #pragma unroll
        for (int i = 0; i < 4; i++)
            #pragma unroll
            for (int j = 0; j < 4; j++) acc[i][j] = 0ull;
        #pragma unroll 8
        for (int kk = 0; kk < 64; kk++) {
            float4 q4 = *(const float4*)&Qt[kk * QTP + r0p];
            ulonglong2 b01 = *(const ulonglong2*)&KVt[kk * KTP + c0p];
            ulonglong2 b23 = *(const ulonglong2*)&KVt[kk * KTP + c0p + 4];
            float qa[4] = {q4.x, q4.y, q4.z, q4.w};
            #pragma unroll
            for (int i = 0; i < 4; i++) {
                ull A = bc2(qa[i]);
                ffma2(acc[i][0], A, b01.x);
                ffma2(acc[i][1], A, b01.y);
                ffma2(acc[i][2], A, b23.x);
                ffma2(acc[i][3], A, b23.y);
            }
        }
        #pragma unroll
        for (int i = 0; i < 4; i++) {
            float2 u0 = upk2(acc[i][0]), u1 = upk2(acc[i][1]);
            float2 u2 = upk2(acc[i][2]), u3 = upk2(acc[i][3]);
            float* dst = &S[(r0p + i) * SPITCH + ch * 128 + c0p];
            *(float4*)dst       = make_float4(u0.x, u0.y, u1.x, u1.y);
            *(float4*)(dst + 4) = make_float4(u2.x, u2.y, u3.x, u3.y);
        }
    }
    __syncthreads();

    int warp = tid >> 5, lane = tid & 31;
    float wa0g = __ldg(&g_alphas[b*3+0]);
    float wa1g = __ldg(&g_alphas[b*3+1]);
    float wa2g = __ldg(&g_alphas[b*3+2]);
    for (int r = warp; r < 64; r += 8) {
        float* Sr = S + r * SPITCH;
        int n = rt * 64 + r;
        const unsigned* p0 = g_packed + ((size_t)(0*BATCH + b) * SEQ + n) * 16;
        const unsigned* p1 = g_packed + ((size_t)(1*BATCH + b) * SEQ + n) * 16;
        const unsigned* p2 = g_packed + ((size_t)(2*BATCH + b) * SEQ + n) * 16;

        float mx = -1e30f;
        #pragma unroll
        for (int it = 0; it < 16; it++) mx = fmaxf(mx, Sr[it * 32 + lane]);
        #pragma unroll
        for (int o = 16; o; o >>= 1) mx = fmaxf(mx, __shfl_xor_sync(0xffffffffu, mx, o));

        float z0 = 0.f, z1 = 0.f, z2 = 0.f;
        #pragma unroll
        for (int it = 0; it < 16; it++) {
            int c = it * 32 + lane;
            float e = __expf(Sr[c] - mx);
            Sr[c] = e;
            unsigned w0 = __ldg(p0 + it), w1 = __ldg(p1 + it), w2 = __ldg(p2 + it);
            if (!((w0 >> lane) & 1)) z0 += e;
            if (!((w1 >> lane) & 1)) z1 += e;
            if (!((w2 >> lane) & 1)) z2 += e;
        }
        #pragma unroll
        for (int o = 16; o; o >>= 1) {
            z0 += __shfl_xor_sync(0xffffffffu, z0, o);
            z1 += __shfl_xor_sync(0xffffffffu, z1, o);
            z2 += __shfl_xor_sync(0xffffffffu, z2, o);
        }
        float wa0 = wa0g / z0, wa1 = wa1g / z1, wa2 = wa2g / z2;
        #pragma unroll
        for (int it = 0; it < 16; it++) {
            int c = it * 32 + lane;
            unsigned w0 = __ldg(p0 + it), w1 = __ldg(p1 + it), w2 = __ldg(p2 + it);
            float coef = (((w0 >> lane) & 1) ? 0.f : wa0)
                       + (((w1 >> lane) & 1) ? 0.f : wa1)
                       + (((w2 >> lane) & 1) ? 0.f : wa2);
            Sr[c] *= coef;
        }
    }

    // phase 3: split-m over 2 groups
    int g   = tid >> 7;
    int lt  = tid & 127;
    int r03 = (lt >> 3) * 4, c03 = (lt & 7) * 8;
    ull acc3[4][4];
    #pragma unroll
    for (int i = 0; i < 4; i++)
        #pragma unroll
        for (int j = 0; j < 4; j++) acc3[i][j] = 0ull;

    float* Vbase = KVt + g * 4096;
    for (int vt = 0; vt < 4; vt++) {
        __syncthreads();
        {
            const float4* src = (const float4*)(Vg + (vt * 2 + g) * 64 * DK);
            float4* dst = (float4*)Vbase;
            #pragma unroll
            for (int it = 0; it < 8; it++) dst[lt + it * 128] = src[lt + it * 128];
        }
        __syncthreads();
        int mg0 = (vt * 2 + g) * 64;
        #pragma unroll 4
        for (int mm = 0; mm < 64; mm++) {
            int mg = mg0 + mm;
            float a0 = S[(r03+0) * SPITCH + mg];
            float a1 = S[(r03+1) * SPITCH + mg];
            float a2 = S[(r03+2) * SPITCH + mg];
            float a3 = S[(r03+3) * SPITCH + mg];
            ulonglong2 v01 = *(const ulonglong2*)&Vbase[mm * 64 + c03];
            ulonglong2 v23 = *(const ulonglong2*)&Vbase[mm * 64 + c03 + 4];
            float aa[4] = {a0, a1, a2, a3};
            #pragma unroll
            for (int i = 0; i < 4; i++) {
                ull A = bc2(aa[i]);
                ffma2(acc3[i][0], A, v01.x);
                ffma2(acc3[i][1], A, v01.y);
                ffma2(acc3[i][2], A, v23.x);
                ffma2(acc3[i][3], A, v23.y);
            }
        }
    }
    __syncthreads();
    float* Sc = Qt;
    if (g == 1) {
        #pragma unroll
        for (int i = 0; i < 4; i++) {
            float2 u0 = upk2(acc3[i][0]), u1 = upk2(acc3[i][1]);
            float2 u2 = upk2(acc3[i][2]), u3 = upk2(acc3[i][3]);
            float* dst = &Sc[(r03 + i) * 64 + c03];
            *(float4*)dst       = make_float4(u0.x, u0.y, u1.x, u1.y);
            *(float4*)(dst + 4) = make_float4(u2.x, u2.y, u3.x, u3.y);
        }
    }
    __syncthreads();
    if (g == 0) {
        #pragma unroll
        for (int i = 0; i < 4; i++) {
            float2 u0 = upk2(acc3[i][0]), u1 = upk2(acc3[i][1]);
            float2 u2 = upk2(acc3[i][2]), u3 = upk2(acc3[i][3]);
            const float* pp = &Sc[(r03 + i) * 64 + c03];
            float4 p0 = *(const float4*)pp;
            float4 p1 = *(const float4*)(pp + 4);
            size_t off = ((size_t)(b * SEQ + rt * 64 + r03 + i) * HEADS + h) * DK + c03;
            uint4 o0 = make_uint4(packbf(u0.x + p0.x), packbf(u0.y + p0.y),
                                  packbf(u1.x + p0.z), packbf(u1.y + p0.w));
            uint4 o1 = make_uint4(packbf(u2.x + p1.x), packbf(u2.y + p1.y),
                                  packbf(u3.x + p1.z), packbf(u3.y + p1.w));
            *(uint4*)&g_abf[off] = o0;
            *(uint4*)&g_abf[off + 4] = o1;
        }
    }
}

// ---- launch ----
extern "C" void kernel_launch(void* const* d_in, const int* in_sizes, int n_in,
                              void* d_out, int out_size) {
    const float* v = (const float*)d_in[0];
    const float* k = (const float*)d_in[1];
    const float* q = (const float*)d_in[2];
    const void*  masks = d_in[3];
    const float* Wv = (const float*)d_in[6];
    const float* bv = (const float*)d_in[7];
    const float* Wk = (const float*)d_in[8];
    const float* bk = (const float*)d_in[9];
    const float* Wq = (const float*)d_in[10];
    const float* bq = (const float*)d_in[11];
    const float* Wm = (const float*)d_in[12];
    const float* bm = (const float*)d_in[13];
    const float* pool_w = (const float*)d_in[14];
    const float* pool_b = (const float*)d_in[15];
    const float* w1 = (const float*)d_in[16];
    const float* w2 = (const float*)d_in[17];
    const float* b2 = (const float*)d_in[18];
    float* out = (float*)d_out;

    static cudaStream_t s1 = 0, s2 = 0;
    static cudaEvent_t evR = 0, ev1 = 0, ev2 = 0;
    if (!s1) {
        cudaStreamCreateWithFlags(&s1, cudaStreamNonBlocking);
        cudaStreamCreateWithFlags(&s2, cudaStreamNonBlocking);
        cudaEventCreateWithFlags(&evR, cudaEventDisableTiming);
        cudaEventCreateWithFlags(&ev1, cudaEventDisableTiming);
        cudaEventCreateWithFlags(&ev2, cudaEventDisableTiming);
        cudaFuncSetAttribute(attn_kernel, cudaFuncAttributeMaxDynamicSharedMemorySize, ATTN_SMEM);
    }

    cudaEventRecord(evR, 0);
    cudaStreamWaitEvent(s1, evR, 0);
    cudaStreamWaitEvent(s2, evR, 0);

    route_pool<<<BATCH, 256, 0, s1>>>(v, pool_w, pool_b);
    route_mlp<<<BATCH, 384, 0, s1>>>(w1, w2, b2);
    cudaEventRecord(ev1, s1);

    detect_mask_mode<<<1, 256, 0, s2>>>((const unsigned*)masks);
    pack_masks<<<ORDERS * BATCH * SEQ / 8, 256, 0, s2>>>(masks);
    cudaEventRecord(ev2, s2);

    // main: convert inputs + weights, then tensor-core QKV
    conv_x<<<dim3(BATCH * SEQ * HIDDEN / 1024, 3), 256>>>(q, k, v);
    conv_w<<<dim3(K2 / 1024, 4), 256>>>(Wq, Wk, Wv, Wm);

    dim3 gq(HIDDEN / 128, (BATCH * SEQ) / 128, 3);   // (6, 32, 3)
    gemm_qkv_bf<<<gq, 256>>>(bq, bk, bv);

    cudaStreamWaitEvent(0, ev1, 0);
    cudaStreamWaitEvent(0, ev2, 0);

    attn_kernel<<<dim3(SEQ / 64, HEADS, BATCH), 256, ATTN_SMEM>>>();

    dim3 gg(HIDDEN / 128, (BATCH * SEQ) / 128);      // (6, 32)
    gemm_out_bf<<<gg, 256>>>(bm, out);
}

// round 9
// speedup vs baseline: 2.9841x; 1.2739x over previous
#include <cuda_runtime.h>
#include <cuda_bf16.h>
#include <math.h>

#define HIDDEN 768
#define HEADS  12
#define DK     64
#define BATCH  8
#define SEQ    512
#define ORDERS 3
#define NEGV   -1e9f
#define K2     (768 * 768)
typedef unsigned long long ull;

// q/k/v/atted stored PACKED bf16-split: (lo<<16 | hi)
__device__ unsigned g_qh[BATCH * HEADS * SEQ * DK];
__device__ unsigned g_kh[BATCH * HEADS * SEQ * DK];
__device__ unsigned g_vh[BATCH * HEADS * SEQ * DK];
__device__ float g_pooled[BATCH * HIDDEN];
__device__ float g_alphas[BATCH * ORDERS];
__device__ int   g_mask_mode;
__device__ unsigned g_packed[ORDERS * BATCH * SEQ * 16];
__device__ unsigned g_qbf[BATCH * SEQ * HIDDEN];
__device__ unsigned g_kbf[BATCH * SEQ * HIDDEN];
__device__ unsigned g_vbf[BATCH * SEQ * HIDDEN];
__device__ unsigned g_abf[BATCH * SEQ * HIDDEN];
__device__ unsigned g_wbf[4 * K2];

__device__ __forceinline__ unsigned packbf(float x) {
    __nv_bfloat16 h = __float2bfloat16_rn(x);
    float hf = __bfloat162float(h);
    __nv_bfloat16 l = __float2bfloat16_rn(x - hf);
    return ((unsigned)__bfloat16_as_ushort(l) << 16) | (unsigned)__bfloat16_as_ushort(h);
}

#define LDSM4(R, addr) \
    asm volatile("ldmatrix.sync.aligned.m8n8.x4.shared.b16 {%0,%1,%2,%3}, [%4];" \
        : "=r"((R)[0]), "=r"((R)[1]), "=r"((R)[2]), "=r"((R)[3]) : "r"(addr))
#define LDSM4T(R, addr) \
    asm volatile("ldmatrix.sync.aligned.m8n8.x4.trans.shared.b16 {%0,%1,%2,%3}, [%4];" \
        : "=r"((R)[0]), "=r"((R)[1]), "=r"((R)[2]), "=r"((R)[3]) : "r"(addr))
#define MMABF(C, A, B0, B1) \
    asm volatile("mma.sync.aligned.m16n8k16.row.col.f32.bf16.bf16.f32 " \
        "{%0,%1,%2,%3},{%4,%5,%6,%7},{%8,%9},{%0,%1,%2,%3};" \
        : "+f"((C)[0]), "+f"((C)[1]), "+f"((C)[2]), "+f"((C)[3]) \
        : "r"((A)[0]), "r"((A)[1]), "r"((A)[2]), "r"((A)[3]), "r"(B0), "r"(B1))

// ---- conversion kernels ----
__global__ __launch_bounds__(256) void conv_x(const float* __restrict__ q,
                                              const float* __restrict__ k,
                                              const float* __restrict__ v) {
    int z = blockIdx.y;
    const float* src = (z == 0) ? q : (z == 1) ? k : v;
    unsigned* dst = (z == 0) ? g_qbf : (z == 1) ? g_kbf : g_vbf;
    size_t i = (size_t)blockIdx.x * 256 + threadIdx.x;
    float4 x = ((const float4*)src)[i];
    ((uint4*)dst)[i] = make_uint4(packbf(x.x), packbf(x.y), packbf(x.z), packbf(x.w));
}
__global__ __launch_bounds__(256) void conv_w(const float* __restrict__ wq,
                                              const float* __restrict__ wk,
                                              const float* __restrict__ wv,
                                              const float* __restrict__ wm) {
    int z = blockIdx.y;
    const float* src = (z == 0) ? wq : (z == 1) ? wk : (z == 2) ? wv : wm;
    unsigned* dst = g_wbf + (size_t)z * K2;
    size_t i = (size_t)blockIdx.x * 256 + threadIdx.x;
    float4 x = ((const float4*)src)[i];
    ((uint4*)dst)[i] = make_uint4(packbf(x.x), packbf(x.y), packbf(x.z), packbf(x.w));
}

// ---- mask detection + packing ----
__global__ void detect_mask_mode(const unsigned* __restrict__ m) {
    __shared__ int sflags;
    if (threadIdx.x == 0) sflags = 0;
    __syncthreads();
    int local = 0;
    for (int i = threadIdx.x; i < 16384; i += 256) {
        unsigned w = m[i];
        if (w == 0x3F800000u) local |= 1;
        else if (w != 0u && w != 1u) local |= 2;
    }
    if (local) atomicOr(&sflags, local);
    __syncthreads();
    if (threadIdx.x == 0)
        g_mask_mode = (sflags & 1) ? 2 : ((sflags & 2) ? 0 : 1);
}
__global__ __launch_bounds__(256) void pack_masks(const void* __restrict__ masks) {
    int mode = g_mask_mode;
    int warp = threadIdx.x >> 5, lane = threadIdx.x & 31;
    int row = blockIdx.x * 8 + warp;
    size_t base = (size_t)row * SEQ;
    #pragma unroll 4
    for (int w16 = 0; w16 < 16; w16++) {
        int c = w16 * 32 + lane;
        bool bit;
        if (mode == 1)      bit = ((const int*)masks)[base + c] != 0;
        else if (mode == 2) bit = ((const float*)masks)[base + c] != 0.f;
        else                bit = ((const unsigned char*)masks)[base + c] != 0;
        unsigned bal = __ballot_sync(0xffffffffu, bit);
        if (lane == 0) g_packed[row * 16 + w16] = bal;
    }
}

// ---- routing 1 ----
__global__ __launch_bounds__(256) void route_pool(const float* __restrict__ v,
                                                  const float* __restrict__ pool_w,
                                                  const float* __restrict__ pool_b) {
    int b = blockIdx.x;
    int tid = threadIdx.x, warp = tid >> 5, lane = tid & 31;
    __shared__ float sc[SEQ];
    __shared__ float red[8], red2[8];
    __shared__ float pw[HIDDEN];
    for (int d = tid; d < HIDDEN; d += 256) pw[d] = pool_w[d];
    __syncthreads();
    for (int n = warp; n < SEQ; n += 8) {
        const float* vp = v + ((size_t)b * SEQ + n) * HIDDEN;
        float dot = 0.f, asum = 0.f;
        #pragma unroll 4
        for (int d = lane; d < HIDDEN; d += 32) {
            float x = vp[d];
            dot += x * pw[d];
            asum += fabsf(x);
        }
        #pragma unroll
        for (int o = 16; o; o >>= 1) {
            dot  += __shfl_xor_sync(0xffffffffu, dot, o);
            asum += __shfl_xor_sync(0xffffffffu, asum, o);
        }
        if (lane == 0) sc[n] = (asum == 0.f) ? NEGV : (dot + pool_b[0]);
    }
    __syncthreads();
    float m = fmaxf(sc[tid], sc[tid + 256]);
    #pragma unroll
    for (int o = 16; o; o >>= 1) m = fmaxf(m, __shfl_xor_sync(0xffffffffu, m, o));
    if (lane == 0) red[warp] = m;
    __syncthreads();
    if (tid == 0) {
        float t = red[0];
        for (int i = 1; i < 8; i++) t = fmaxf(t, red[i]);
        red[0] = t;
    }
    __syncthreads();
    m = red[0];
    float e0 = __expf(sc[tid] - m), e1 = __expf(sc[tid + 256] - m);
    float s = e0 + e1;
    #pragma unroll
    for (int o = 16; o; o >>= 1) s += __shfl_xor_sync(0xffffffffu, s, o);
    if (lane == 0) red2[warp] = s;
    __syncthreads();
    if (tid == 0) {
        float t = 0.f;
        for (int i = 0; i < 8; i++) t += red2[i];
        red2[0] = t;
    }
    __syncthreads();
    float inv = 1.f / red2[0];
    sc[tid] = e0 * inv;
    sc[tid + 256] = e1 * inv;
    __syncthreads();
    float a0 = 0.f, a1 = 0.f, a2 = 0.f;
    #pragma unroll 4
    for (int n = 0; n < SEQ; n++) {
        float p = sc[n];
        const float* vp = v + ((size_t)b * SEQ + n) * HIDDEN;
        a0 += vp[tid] * p;
        a1 += vp[tid + 256] * p;
        a2 += vp[tid + 512] * p;
    }
    g_pooled[b * HIDDEN + tid]       = a0;
    g_pooled[b * HIDDEN + tid + 256] = a1;
    g_pooled[b * HIDDEN + tid + 512] = a2;
}

// ---- routing 2 ----
__global__ __launch_bounds__(384) void route_mlp(const float* __restrict__ w1,
                                                 const float* __restrict__ w2,
                                                 const float* __restrict__ b2) {
    int b = blockIdx.x, tid = threadIdx.x;
    __shared__ float pl[HIDDEN];
    __shared__ float pred[12 * 3];
    for (int d = tid; d < HIDDEN; d += 384) pl[d] = g_pooled[b * HIDDEN + d];
    __syncthreads();
    float acc = 0.f;
    #pragma unroll 16
    for (int k = 0; k < HIDDEN; k++) acc += pl[k] * __ldg(&w1[k * 384 + tid]);
    float hv = fmaxf(acc, 0.f);
    float p0 = hv * w2[tid * 3 + 0];
    float p1 = hv * w2[tid * 3 + 1];
    float p2 = hv * w2[tid * 3 + 2];
    #pragma unroll
    for (int o = 16; o; o >>= 1) {
        p0 += __shfl_xor_sync(0xffffffffu, p0, o);
        p1 += __shfl_xor_sync(0xffffffffu, p1, o);
        p2 += __shfl_xor_sync(0xffffffffu, p2, o);
    }
    int warp = tid >> 5;
    if ((tid & 31) == 0) { pred[warp*3] = p0; pred[warp*3+1] = p1; pred[warp*3+2] = p2; }
    __syncthreads();
    if (tid == 0) {
        float l0 = b2[0], l1 = b2[1], l2 = b2[2];
        for (int w = 0; w < 12; w++) { l0 += pred[w*3]; l1 += pred[w*3+1]; l2 += pred[w*3+2]; }
        float mm = fmaxf(l0, fmaxf(l1, l2));
        float e0 = __expf(l0 - mm), e1 = __expf(l1 - mm), e2 = __expf(l2 - mm);
        float z = e0 + e1 + e2;
        g_alphas[b*3+0] = e0 / z; g_alphas[b*3+1] = e1 / z; g_alphas[b*3+2] = e2 / z;
    }
}

// ---- bf16-split tensor-core GEMM ----
// omode 0: fp32 out[i*768+j]; omode 1: packed head layout (unsigned)
__device__ __forceinline__ void gemm_bf_body(const unsigned* __restrict__ Xp,
                                             const unsigned* __restrict__ Wp,
                                             const float* __restrict__ bias,
                                             void* __restrict__ outp,
                                             float scale, int omode,
                                             int row0, int col0) {
    __shared__ __align__(16) __nv_bfloat16 Ah[128][40], Al[128][40];
    __shared__ __align__(16) __nv_bfloat16 Bh[32][136], Bl[32][136];
    int tid = threadIdx.x;
    int wid = tid >> 5, lane = tid & 31;
    int wm = wid & 1, wn = wid >> 1;

    float acc[4][4][4];
    #pragma unroll
    for (int i = 0; i < 4; i++)
        #pragma unroll
        for (int j = 0; j < 4; j++)
            #pragma unroll
            for (int c = 0; c < 4; c++) acc[i][j][c] = 0.f;

    unsigned aaddr_h[4], aaddr_l[4];
    #pragma unroll
    for (int mt = 0; mt < 4; mt++) {
        aaddr_h[mt] = (unsigned)__cvta_generic_to_shared(
            &Ah[wm * 64 + mt * 16 + (lane & 15)][(lane >> 4) << 3]);
        aaddr_l[mt] = (unsigned)__cvta_generic_to_shared(
            &Al[wm * 64 + mt * 16 + (lane & 15)][(lane >> 4) << 3]);
    }
    unsigned baddr_h[2], baddr_l[2];
    #pragma unroll
    for (int nb = 0; nb < 2; nb++) {
        int kr = (lane & 7) + (((lane >> 3) & 1) << 3);
        int nc = wn * 32 + nb * 16 + ((lane >> 4) << 3);
        baddr_h[nb] = (unsigned)__cvta_generic_to_shared(&Bh[kr][nc]);
        baddr_l[nb] = (unsigned)__cvta_generic_to_shared(&Bl[kr][nc]);
    }

    for (int kt = 0; kt < 768; kt += 32) {
        __syncthreads();
        #pragma unroll
        for (int i = 0; i < 4; i++) {
            int e = tid + i * 256;
            int r = e >> 3, k0 = (e & 7) * 4;
            uint4 x = *(const uint4*)&Xp[(size_t)(row0 + r) * 768 + kt + k0];
            *(unsigned*)&Ah[r][k0]     = __byte_perm(x.x, x.y, 0x5410);
            *(unsigned*)&Al[r][k0]     = __byte_perm(x.x, x.y, 0x7632);
            *(unsigned*)&Ah[r][k0 + 2] = __byte_perm(x.z, x.w, 0x5410);
            *(unsigned*)&Al[r][k0 + 2] = __byte_perm(x.z, x.w, 0x7632);
        }
        #pragma unroll
        for (int i = 0; i < 4; i++) {
            int e = tid + i * 256;
            int kk = e >> 5, n0 = (e & 31) * 4;
            uint4 x = *(const uint4*)&Wp[(size_t)(kt + kk) * 768 + col0 + n0];
            *(unsigned*)&Bh[kk][n0]     = __byte_perm(x.x, x.y, 0x5410);
            *(unsigned*)&Bl[kk][n0]     = __byte_perm(x.x, x.y, 0x7632);
            *(unsigned*)&Bh[kk][n0 + 2] = __byte_perm(x.z, x.w, 0x5410);
            *(unsigned*)&Bl[kk][n0 + 2] = __byte_perm(x.z, x.w, 0x7632);
        }
        __syncthreads();
        #pragma unroll
        for (int ks = 0; ks < 2; ks++) {
            unsigned koff = ks * 32;
            unsigned ah[4][4], al[4][4], bh[2][4], bl[2][4];
            #pragma unroll
            for (int mt = 0; mt < 4; mt++) {
                LDSM4(ah[mt], aaddr_h[mt] + koff);
                LDSM4(al[mt], aaddr_l[mt] + koff);
            }
            #pragma unroll
            for (int nb = 0; nb < 2; nb++) {
                LDSM4T(bh[nb], baddr_h[nb] + ks * 16 * 272);
                LDSM4T(bl[nb], baddr_l[nb] + ks * 16 * 272);
            }
            #pragma unroll
            for (int mt = 0; mt < 4; mt++)
                #pragma unroll
                for (int nt = 0; nt < 4; nt++) {
                    unsigned bh0 = bh[nt >> 1][(nt & 1) * 2];
                    unsigned bh1 = bh[nt >> 1][(nt & 1) * 2 + 1];
                    unsigned bl0 = bl[nt >> 1][(nt & 1) * 2];
                    unsigned bl1 = bl[nt >> 1][(nt & 1) * 2 + 1];
                    MMABF(acc[mt][nt], ah[mt], bh0, bh1);
                    MMABF(acc[mt][nt], ah[mt], bl0, bl1);
                    MMABF(acc[mt][nt], al[mt], bh0, bh1);
                }
        }
    }

    int rbase = row0 + wm * 64, cbase = col0 + wn * 32;
    #pragma unroll
    for (int mt = 0; mt < 4; mt++) {
        #pragma unroll
        for (int nt = 0; nt < 4; nt++) {
            int gj = cbase + nt * 8 + (lane & 3) * 2;
            float b0 = __ldg(&bias[gj]), b1 = __ldg(&bias[gj + 1]);
            int r_lo = rbase + mt * 16 + (lane >> 2);
            int r_hi = r_lo + 8;
            float c00 = (acc[mt][nt][0] + b0) * scale;
            float c01 = (acc[mt][nt][1] + b1) * scale;
            float c10 = (acc[mt][nt][2] + b0) * scale;
            float c11 = (acc[mt][nt][3] + b1) * scale;
            if (omode == 1) {
                unsigned* out = (unsigned*)outp;
                int bb0 = r_lo >> 9, n0 = r_lo & 511;
                int h = gj >> 6, d = gj & 63;
                *(uint2*)&out[(((size_t)bb0 * HEADS + h) * SEQ + n0) * DK + d] =
                    make_uint2(packbf(c00), packbf(c01));
                int bb1 = r_hi >> 9, n1 = r_hi & 511;
                *(uint2*)&out[(((size_t)bb1 * HEADS + h) * SEQ + n1) * DK + d] =
                    make_uint2(packbf(c10), packbf(c11));
            } else {
                float* out = (float*)outp;
                *(float2*)&out[(size_t)r_lo * 768 + gj] = make_float2(c00, c01);
                *(float2*)&out[(size_t)r_hi * 768 + gj] = make_float2(c10, c11);
            }
        }
    }
}

__global__ __launch_bounds__(256) void gemm_qkv_bf(const float* __restrict__ bq,
                                                   const float* __restrict__ bk,
                                                   const float* __restrict__ bv) {
    int z = blockIdx.z;
    const unsigned* Xp; const unsigned* Wp; const float* bias; unsigned* out; float scale;
    if (z == 0)      { Xp = g_qbf; Wp = g_wbf;          bias = bq; out = g_qh; scale = 0.125f; }
    else if (z == 1) { Xp = g_kbf; Wp = g_wbf + K2;     bias = bk; out = g_kh; scale = 1.f; }
    else             { Xp = g_vbf; Wp = g_wbf + 2 * K2; bias = bv; out = g_vh; scale = 1.f; }
    gemm_bf_body(Xp, Wp, bias, out, scale, 1, blockIdx.y * 128, blockIdx.x * 128);
}

__global__ __launch_bounds__(256) void gemm_out_bf(const float* __restrict__ bias,
                                                   float* __restrict__ out) {
    gemm_bf_body(g_abf, g_wbf + 3 * K2, bias, out, 1.f, 0,
                 blockIdx.y * 128, blockIdx.x * 128);
}

// ---- fused attention, tensor-core phases 1 & 3 ----
#define SPITCH 516
#define QP 72
#define KP 72
#define AP 136
// byte offsets in dynamic smem
#define OFF_S  0
#define OFF_Q  132096
#define OFF_W  150528
#define ATTN_SMEM (OFF_W + 71680)

__global__ __launch_bounds__(256) void attn_kernel() {
    extern __shared__ char smc[];
    float* S = (float*)(smc + OFF_S);
    __nv_bfloat16* Qh = (__nv_bfloat16*)(smc + OFF_Q);
    __nv_bfloat16* Ql = (__nv_bfloat16*)(smc + OFF_Q + 9216);
    __nv_bfloat16* Kh = (__nv_bfloat16*)(smc + OFF_W);
    __nv_bfloat16* Kl = (__nv_bfloat16*)(smc + OFF_W + 18432);
    __nv_bfloat16* Ah = (__nv_bfloat16*)(smc + OFF_W);
    __nv_bfloat16* Al = (__nv_bfloat16*)(smc + OFF_W + 17408);
    __nv_bfloat16* Vh = (__nv_bfloat16*)(smc + OFF_W + 34816);
    __nv_bfloat16* Vl = (__nv_bfloat16*)(smc + OFF_W + 53248);

    int rt = blockIdx.x, h = blockIdx.y, b = blockIdx.z;
    int tid = threadIdx.x;
    int wid = tid >> 5, lane = tid & 31;

    const unsigned* Qg = g_qh + (((size_t)(b * HEADS + h)) * SEQ + rt * 64) * DK;
    const unsigned* Kg = g_kh + ((size_t)(b * HEADS + h)) * SEQ * DK;
    const unsigned* Vg = g_vh + ((size_t)(b * HEADS + h)) * SEQ * DK;

    // load Q (64x64 packed) -> Qh/Ql
    #pragma unroll
    for (int i = 0; i < 8; i++) {
        int idx = tid + i * 256;
        int r = idx >> 5, c2 = (idx & 31) * 2;
        uint2 u = *(const uint2*)&Qg[r * DK + c2];
        *(unsigned*)&Qh[r * QP + c2] = __byte_perm(u.x, u.y, 0x5410);
        *(unsigned*)&Ql[r * QP + c2] = __byte_perm(u.x, u.y, 0x7632);
    }

    // ---- phase 1: S = Q K^T, 4 chunks of 128 cols ----
    int wm = wid & 1, wn = wid >> 1;
    unsigned qah[2], qal[2];
    #pragma unroll
    for (int mt = 0; mt < 2; mt++) {
        qah[mt] = (unsigned)__cvta_generic_to_shared(
            &Qh[(wm * 32 + mt * 16 + (lane & 15)) * QP + ((lane >> 4) << 3)]);
        qal[mt] = (unsigned)__cvta_generic_to_shared(
            &Ql[(wm * 32 + mt * 16 + (lane & 15)) * QP + ((lane >> 4) << 3)]);
    }
    unsigned kah[2], kal[2];
    #pragma unroll
    for (int nb = 0; nb < 2; nb++) {
        kah[nb] = (unsigned)__cvta_generic_to_shared(
            &Kh[(wn * 32 + nb * 16 + (lane & 15)) * KP + ((lane >> 4) << 3)]);
        kal[nb] = (unsigned)__cvta_generic_to_shared(
            &Kl[(wn * 32 + nb * 16 + (lane & 15)) * KP + ((lane >> 4) << 3)]);
    }

    for (int ch = 0; ch < 4; ch++) {
        __syncthreads();
        #pragma unroll
        for (int i = 0; i < 16; i++) {
            int idx = tid + i * 256;
            int r = idx >> 5, c2 = (idx & 31) * 2;
            uint2 u = *(const uint2*)&Kg[(ch * 128 + r) * DK + c2];
            *(unsigned*)&Kh[r * KP + c2] = __byte_perm(u.x, u.y, 0x5410);
            *(unsigned*)&Kl[r * KP + c2] = __byte_perm(u.x, u.y, 0x7632);
        }
        __syncthreads();
        float acc1[2][4][4];
        #pragma unroll
        for (int i = 0; i < 2; i++)
            #pragma unroll
            for (int j = 0; j < 4; j++)
                #pragma unroll
                for (int c = 0; c < 4; c++) acc1[i][j][c] = 0.f;
        #pragma unroll
        for (int kc = 0; kc < 4; kc++) {
            unsigned koff = kc * 32;
            unsigned ah[2][4], al[2][4], bh[2][4], bl[2][4];
            #pragma unroll
            for (int mt = 0; mt < 2; mt++) {
                LDSM4(ah[mt], qah[mt] + koff);
                LDSM4(al[mt], qal[mt] + koff);
            }
            #pragma unroll
            for (int nb = 0; nb < 2; nb++) {
                LDSM4(bh[nb], kah[nb] + koff);
                LDSM4(bl[nb], kal[nb] + koff);
            }
            #pragma unroll
            for (int mt = 0; mt < 2; mt++)
                #pragma unroll
                for (int nt = 0; nt < 4; nt++) {
                    int nb = nt >> 1, hi = nt & 1;
                    unsigned b0h = bh[nb][hi], b1h = bh[nb][hi + 2];
                    unsigned b0l = bl[nb][hi], b1l = bl[nb][hi + 2];
                    MMABF(acc1[mt][nt], ah[mt], b0h, b1h);
                    MMABF(acc1[mt][nt], ah[mt], b0l, b1l);
                    MMABF(acc1[mt][nt], al[mt], b0h, b1h);
                }
        }
        #pragma unroll
        for (int mt = 0; mt < 2; mt++)
            #pragma unroll
            for (int nt = 0; nt < 4; nt++) {
                int r = wm * 32 + mt * 16 + (lane >> 2);
                int c = ch * 128 + wn * 32 + nt * 8 + (lane & 3) * 2;
                *(float2*)&S[r * SPITCH + c] = make_float2(acc1[mt][nt][0], acc1[mt][nt][1]);
                *(float2*)&S[(r + 8) * SPITCH + c] = make_float2(acc1[mt][nt][2], acc1[mt][nt][3]);
            }
    }
    __syncthreads();

    // ---- phase 2: masked softmax algebra (unchanged) ----
    float wa0g = __ldg(&g_alphas[b*3+0]);
    float wa1g = __ldg(&g_alphas[b*3+1]);
    float wa2g = __ldg(&g_alphas[b*3+2]);
    for (int r = wid; r < 64; r += 8) {
        float* Sr = S + r * SPITCH;
        int n = rt * 64 + r;
        const unsigned* p0 = g_packed + ((size_t)(0*BATCH + b) * SEQ + n) * 16;
        const unsigned* p1 = g_packed + ((size_t)(1*BATCH + b) * SEQ + n) * 16;
        const unsigned* p2 = g_packed + ((size_t)(2*BATCH + b) * SEQ + n) * 16;

        float mx = -1e30f;
        #pragma unroll
        for (int it = 0; it < 16; it++) mx = fmaxf(mx, Sr[it * 32 + lane]);
        #pragma unroll
        for (int o = 16; o; o >>= 1) mx = fmaxf(mx, __shfl_xor_sync(0xffffffffu, mx, o));

        float z0 = 0.f, z1 = 0.f, z2 = 0.f;
        #pragma unroll
        for (int it = 0; it < 16; it++) {
            int c = it * 32 + lane;
            float e = __expf(Sr[c] - mx);
            Sr[c] = e;
            unsigned w0 = __ldg(p0 + it), w1 = __ldg(p1 + it), w2 = __ldg(p2 + it);
            if (!((w0 >> lane) & 1)) z0 += e;
            if (!((w1 >> lane) & 1)) z1 += e;
            if (!((w2 >> lane) & 1)) z2 += e;
        }
        #pragma unroll
        for (int o = 16; o; o >>= 1) {
            z0 += __shfl_xor_sync(0xffffffffu, z0, o);
            z1 += __shfl_xor_sync(0xffffffffu, z1, o);
            z2 += __shfl_xor_sync(0xffffffffu, z2, o);
        }
        float wa0 = wa0g / z0, wa1 = wa1g / z1, wa2 = wa2g / z2;
        #pragma unroll
        for (int it = 0; it < 16; it++) {
            int c = it * 32 + lane;
            unsigned w0 = __ldg(p0 + it), w1 = __ldg(p1 + it), w2 = __ldg(p2 + it);
            float coef = (((w0 >> lane) & 1) ? 0.f : wa0)
                       + (((w1 >> lane) & 1) ? 0.f : wa1)
                       + (((w2 >> lane) & 1) ? 0.f : wa2);
            Sr[c] *= coef;
        }
    }

    // ---- phase 3: O = A V, tensor cores, 4 chunks of 128 k-rows ----
    float acc3[2][2][4];
    #pragma unroll
    for (int i = 0; i < 2; i++)
        #pragma unroll
        for (int j = 0; j < 2; j++)
            #pragma unroll
            for (int c = 0; c < 4; c++) acc3[i][j][c] = 0.f;

    unsigned aah[2], aal[2];
    #pragma unroll
    for (int mt = 0; mt < 2; mt++) {
        aah[mt] = (unsigned)__cvta_generic_to_shared(
            &Ah[(wm * 32 + mt * 16 + (lane & 15)) * AP + ((lane >> 4) << 3)]);
        aal[mt] = (unsigned)__cvta_generic_to_shared(
            &Al[(wm * 32 + mt * 16 + (lane & 15)) * AP + ((lane >> 4) << 3)]);
    }
    int vkr = (lane & 7) + (((lane >> 3) & 1) << 3);
    int vnc = wn * 16 + ((lane >> 4) << 3);
    unsigned vah = (unsigned)__cvta_generic_to_shared(&Vh[vkr * KP + vnc]);
    unsigned val = (unsigned)__cvta_generic_to_shared(&Vl[vkr * KP + vnc]);

    for (int ch = 0; ch < 4; ch++) {
        __syncthreads();
        // convert A chunk fp32 -> split bf16
        #pragma unroll
        for (int i = 0; i < 16; i++) {
            int idx = tid + i * 256;
            int r = idx >> 6, c2 = (idx & 63) * 2;
            float2 v2 = *(const float2*)&S[r * SPITCH + ch * 128 + c2];
            unsigned pa = packbf(v2.x), pb = packbf(v2.y);
            *(unsigned*)&Ah[r * AP + c2] = __byte_perm(pa, pb, 0x5410);
            *(unsigned*)&Al[r * AP + c2] = __byte_perm(pa, pb, 0x7632);
        }
        // load V chunk packed
        #pragma unroll
        for (int i = 0; i < 16; i++) {
            int idx = tid + i * 256;
            int r = idx >> 5, c2 = (idx & 31) * 2;
            uint2 u = *(const uint2*)&Vg[(ch * 128 + r) * DK + c2];
            *(unsigned*)&Vh[r * KP + c2] = __byte_perm(u.x, u.y, 0x5410);
            *(unsigned*)&Vl[r * KP + c2] = __byte_perm(u.x, u.y, 0x7632);
        }
        __syncthreads();
        #pragma unroll
        for (int kc = 0; kc < 8; kc++) {
            unsigned koff = kc * 32;
            unsigned voff = kc * 16 * (KP * 2);
            unsigned ah[2][4], al[2][4], bh[4], bl[4];
            #pragma unroll
            for (int mt = 0; mt < 2; mt++) {
                LDSM4(ah[mt], aah[mt] + koff);
                LDSM4(al[mt], aal[mt] + koff);
            }
            LDSM4T(bh, vah + voff);
            LDSM4T(bl, val + voff);
            #pragma unroll
            for (int mt = 0; mt < 2; mt++)
                #pragma unroll
                for (int nt = 0; nt < 2; nt++) {
                    unsigned b0h = bh[nt * 2], b1h = bh[nt * 2 + 1];
                    unsigned b0l = bl[nt * 2], b1l = bl[nt * 2 + 1];
                    MMABF(acc3[mt][nt], ah[mt], b0h, b1h);
                    MMABF(acc3[mt][nt], ah[mt], b0l, b1l);
                    MMABF(acc3[mt][nt], al[mt], b0h, b1h);
                }
        }
    }

    // epilogue: pack to g_abf [b*512+n][h*64+d]
    #pragma unroll
    for (int mt = 0; mt < 2; mt++)
        #pragma unroll
        for (int nt = 0; nt < 2; nt++) {
            int r = wm * 32 + mt * 16 + (lane >> 2);
            int c = wn * 16 + nt * 8 + (lane & 3) * 2;
            size_t off0 = (size_t)(b * SEQ + rt * 64 + r) * HIDDEN + h * 64 + c;
            size_t off1 = (size_t)(b * SEQ + rt * 64 + r + 8) * HIDDEN + h * 64 + c;
            *(uint2*)&g_abf[off0] = make_uint2(packbf(acc3[mt][nt][0]), packbf(acc3[mt][nt][1]));
            *(uint2*)&g_abf[off1] = make_uint2(packbf(acc3[mt][nt][2]), packbf(acc3[mt][nt][3]));
        }
}

// ---- launch ----
extern "C" void kernel_launch(void* const* d_in, const int* in_sizes, int n_in,
                              void* d_out, int out_size) {
    const float* v = (const float*)d_in[0];
    const float* k = (const float*)d_in[1];
    const float* q = (const float*)d_in[2];
    const void*  masks = d_in[3];
    const float* Wv = (const float*)d_in[6];
    const float* bv = (const float*)d_in[7];
    const float* Wk = (const float*)d_in[8];
    const float* bk = (const float*)d_in[9];
    const float* Wq = (const float*)d_in[10];
    const float* bq = (const float*)d_in[11];
    const float* Wm = (const float*)d_in[12];
    const float* bm = (const float*)d_in[13];
    const float* pool_w = (const float*)d_in[14];
    const float* pool_b = (const float*)d_in[15];
    const float* w1 = (const float*)d_in[16];
    const float* w2 = (const float*)d_in[17];
    const float* b2 = (const float*)d_in[18];
    float* out = (float*)d_out;

    static cudaStream_t s1 = 0, s2 = 0;
    static cudaEvent_t evR = 0, ev1 = 0, ev2 = 0;
    if (!s1) {
        cudaStreamCreateWithFlags(&s1, cudaStreamNonBlocking);
        cudaStreamCreateWithFlags(&s2, cudaStreamNonBlocking);
        cudaEventCreateWithFlags(&evR, cudaEventDisableTiming);
        cudaEventCreateWithFlags(&ev1, cudaEventDisableTiming);
        cudaEventCreateWithFlags(&ev2, cudaEventDisableTiming);
        cudaFuncSetAttribute(attn_kernel, cudaFuncAttributeMaxDynamicSharedMemorySize, ATTN_SMEM);
    }

    cudaEventRecord(evR, 0);
    cudaStreamWaitEvent(s1, evR, 0);
    cudaStreamWaitEvent(s2, evR, 0);

    route_pool<<<BATCH, 256, 0, s1>>>(v, pool_w, pool_b);
    route_mlp<<<BATCH, 384, 0, s1>>>(w1, w2, b2);
    cudaEventRecord(ev1, s1);

    detect_mask_mode<<<1, 256, 0, s2>>>((const unsigned*)masks);
    pack_masks<<<ORDERS * BATCH * SEQ / 8, 256, 0, s2>>>(masks);
    cudaEventRecord(ev2, s2);

    conv_x<<<dim3(BATCH * SEQ * HIDDEN / 1024, 3), 256>>>(q, k, v);
    conv_w<<<dim3(K2 / 1024, 4), 256>>>(Wq, Wk, Wv, Wm);

    dim3 gq(HIDDEN / 128, (BATCH * SEQ) / 128, 3);
    gemm_qkv_bf<<<gq, 256>>>(bq, bk, bv);

    cudaStreamWaitEvent(0, ev1, 0);
    cudaStreamWaitEvent(0, ev2, 0);

    attn_kernel<<<dim3(SEQ / 64, HEADS, BATCH), 256, ATTN_SMEM>>>();

    dim3 gg(HIDDEN / 128, (BATCH * SEQ) / 128);
    gemm_out_bf<<<gg, 256>>>(bm, out);
}

// round 11
// speedup vs baseline: 3.2267x; 1.0813x over previous
#include <cuda_runtime.h>
#include <cuda_bf16.h>
#include <math.h>

#define HIDDEN 768
#define HEADS  12
#define DK     64
#define BATCH  8
#define SEQ    512
#define ORDERS 3
#define NEGV   -1e9f
#define K2     (768 * 768)
typedef unsigned long long ull;

// q/k/v/atted stored PACKED bf16-split: (lo<<16 | hi)
__device__ unsigned g_qh[BATCH * HEADS * SEQ * DK];
__device__ unsigned g_kh[BATCH * HEADS * SEQ * DK];
__device__ unsigned g_vh[BATCH * HEADS * SEQ * DK];
__device__ float g_pooled[BATCH * HIDDEN];
__device__ float g_alphas[BATCH * ORDERS];
__device__ int   g_mask_mode;
__device__ unsigned g_packed[ORDERS * BATCH * SEQ * 16];
__device__ unsigned g_qbf[BATCH * SEQ * HIDDEN];
__device__ unsigned g_kbf[BATCH * SEQ * HIDDEN];
__device__ unsigned g_vbf[BATCH * SEQ * HIDDEN];
__device__ unsigned g_abf[BATCH * SEQ * HIDDEN];
__device__ unsigned g_wbf[4 * K2];

__device__ __forceinline__ unsigned packbf(float x) {
    __nv_bfloat16 h = __float2bfloat16_rn(x);
    float hf = __bfloat162float(h);
    __nv_bfloat16 l = __float2bfloat16_rn(x - hf);
    return ((unsigned)__bfloat16_as_ushort(l) << 16) | (unsigned)__bfloat16_as_ushort(h);
}

#define LDSM4(R, addr) \
    asm volatile("ldmatrix.sync.aligned.m8n8.x4.shared.b16 {%0,%1,%2,%3}, [%4];" \
        : "=r"((R)[0]), "=r"((R)[1]), "=r"((R)[2]), "=r"((R)[3]) : "r"(addr))
#define LDSM4T(R, addr) \
    asm volatile("ldmatrix.sync.aligned.m8n8.x4.trans.shared.b16 {%0,%1,%2,%3}, [%4];" \
        : "=r"((R)[0]), "=r"((R)[1]), "=r"((R)[2]), "=r"((R)[3]) : "r"(addr))
#define MMABF(C, A, B0, B1) \
    asm volatile("mma.sync.aligned.m16n8k16.row.col.f32.bf16.bf16.f32 " \
        "{%0,%1,%2,%3},{%4,%5,%6,%7},{%8,%9},{%0,%1,%2,%3};" \
        : "+f"((C)[0]), "+f"((C)[1]), "+f"((C)[2]), "+f"((C)[3]) \
        : "r"((A)[0]), "r"((A)[1]), "r"((A)[2]), "r"((A)[3]), "r"(B0), "r"(B1))

// ---- conversion kernels ----
__global__ __launch_bounds__(256) void conv_x(const float* __restrict__ q,
                                              const float* __restrict__ k,
                                              const float* __restrict__ v) {
    int z = blockIdx.y;
    const float* src = (z == 0) ? q : (z == 1) ? k : v;
    unsigned* dst = (z == 0) ? g_qbf : (z == 1) ? g_kbf : g_vbf;
    size_t i = (size_t)blockIdx.x * 256 + threadIdx.x;
    float4 x = ((const float4*)src)[i];
    ((uint4*)dst)[i] = make_uint4(packbf(x.x), packbf(x.y), packbf(x.z), packbf(x.w));
}
__global__ __launch_bounds__(256) void conv_w(const float* __restrict__ wq,
                                              const float* __restrict__ wk,
                                              const float* __restrict__ wv,
                                              const float* __restrict__ wm) {
    int z = blockIdx.y;
    const float* src = (z == 0) ? wq : (z == 1) ? wk : (z == 2) ? wv : wm;
    unsigned* dst = g_wbf + (size_t)z * K2;
    size_t i = (size_t)blockIdx.x * 256 + threadIdx.x;
    float4 x = ((const float4*)src)[i];
    ((uint4*)dst)[i] = make_uint4(packbf(x.x), packbf(x.y), packbf(x.z), packbf(x.w));
}

// ---- mask detection + packing ----
__global__ void detect_mask_mode(const unsigned* __restrict__ m) {
    __shared__ int sflags;
    if (threadIdx.x == 0) sflags = 0;
    __syncthreads();
    int local = 0;
    for (int i = threadIdx.x; i < 16384; i += 256) {
        unsigned w = m[i];
        if (w == 0x3F800000u) local |= 1;
        else if (w != 0u && w != 1u) local |= 2;
    }
    if (local) atomicOr(&sflags, local);
    __syncthreads();
    if (threadIdx.x == 0)
        g_mask_mode = (sflags & 1) ? 2 : ((sflags & 2) ? 0 : 1);
}
__global__ __launch_bounds__(256) void pack_masks(const void* __restrict__ masks) {
    int mode = g_mask_mode;
    int warp = threadIdx.x >> 5, lane = threadIdx.x & 31;
    int row = blockIdx.x * 8 + warp;
    size_t base = (size_t)row * SEQ;
    #pragma unroll 4
    for (int w16 = 0; w16 < 16; w16++) {
        int c = w16 * 32 + lane;
        bool bit;
        if (mode == 1)      bit = ((const int*)masks)[base + c] != 0;
        else if (mode == 2) bit = ((const float*)masks)[base + c] != 0.f;
        else                bit = ((const unsigned char*)masks)[base + c] != 0;
        unsigned bal = __ballot_sync(0xffffffffu, bit);
        if (lane == 0) g_packed[row * 16 + w16] = bal;
    }
}

// ---- routing 1 ----
__global__ __launch_bounds__(256) void route_pool(const float* __restrict__ v,
                                                  const float* __restrict__ pool_w,
                                                  const float* __restrict__ pool_b) {
    int b = blockIdx.x;
    int tid = threadIdx.x, warp = tid >> 5, lane = tid & 31;
    __shared__ float sc[SEQ];
    __shared__ float red[8], red2[8];
    __shared__ float pw[HIDDEN];
    for (int d = tid; d < HIDDEN; d += 256) pw[d] = pool_w[d];
    __syncthreads();
    for (int n = warp; n < SEQ; n += 8) {
        const float* vp = v + ((size_t)b * SEQ + n) * HIDDEN;
        float dot = 0.f, asum = 0.f;
        #pragma unroll 4
        for (int d = lane; d < HIDDEN; d += 32) {
            float x = vp[d];
            dot += x * pw[d];
            asum += fabsf(x);
        }
        #pragma unroll
        for (int o = 16; o; o >>= 1) {
            dot  += __shfl_xor_sync(0xffffffffu, dot, o);
            asum += __shfl_xor_sync(0xffffffffu, asum, o);
        }
        if (lane == 0) sc[n] = (asum == 0.f) ? NEGV : (dot + pool_b[0]);
    }
    __syncthreads();
    float m = fmaxf(sc[tid], sc[tid + 256]);
    #pragma unroll
    for (int o = 16; o; o >>= 1) m = fmaxf(m, __shfl_xor_sync(0xffffffffu, m, o));
    if (lane == 0) red[warp] = m;
    __syncthreads();
    if (tid == 0) {
        float t = red[0];
        for (int i = 1; i < 8; i++) t = fmaxf(t, red[i]);
        red[0] = t;
    }
    __syncthreads();
    m = red[0];
    float e0 = __expf(sc[tid] - m), e1 = __expf(sc[tid + 256] - m);
    float s = e0 + e1;
    #pragma unroll
    for (int o = 16; o; o >>= 1) s += __shfl_xor_sync(0xffffffffu, s, o);
    if (lane == 0) red2[warp] = s;
    __syncthreads();
    if (tid == 0) {
        float t = 0.f;
        for (int i = 0; i < 8; i++) t += red2[i];
        red2[0] = t;
    }
    __syncthreads();
    float inv = 1.f / red2[0];
    sc[tid] = e0 * inv;
    sc[tid + 256] = e1 * inv;
    __syncthreads();
    float a0 = 0.f, a1 = 0.f, a2 = 0.f;
    #pragma unroll 4
    for (int n = 0; n < SEQ; n++) {
        float p = sc[n];
        const float* vp = v + ((size_t)b * SEQ + n) * HIDDEN;
        a0 += vp[tid] * p;
        a1 += vp[tid + 256] * p;
        a2 += vp[tid + 512] * p;
    }
    g_pooled[b * HIDDEN + tid]       = a0;
    g_pooled[b * HIDDEN + tid + 256] = a1;
    g_pooled[b * HIDDEN + tid + 512] = a2;
}

// ---- routing 2 ----
__global__ __launch_bounds__(384) void route_mlp(const float* __restrict__ w1,
                                                 const float* __restrict__ w2,
                                                 const float* __restrict__ b2) {
    int b = blockIdx.x, tid = threadIdx.x;
    __shared__ float pl[HIDDEN];
    __shared__ float pred[12 * 3];
    for (int d = tid; d < HIDDEN; d += 384) pl[d] = g_pooled[b * HIDDEN + d];
    __syncthreads();
    float acc = 0.f;
    #pragma unroll 16
    for (int k = 0; k < HIDDEN; k++) acc += pl[k] * __ldg(&w1[k * 384 + tid]);
    float hv = fmaxf(acc, 0.f);
    float p0 = hv * w2[tid * 3 + 0];
    float p1 = hv * w2[tid * 3 + 1];
    float p2 = hv * w2[tid * 3 + 2];
    #pragma unroll
    for (int o = 16; o; o >>= 1) {
        p0 += __shfl_xor_sync(0xffffffffu, p0, o);
        p1 += __shfl_xor_sync(0xffffffffu, p1, o);
        p2 += __shfl_xor_sync(0xffffffffu, p2, o);
    }
    int warp = tid >> 5;
    if ((tid & 31) == 0) { pred[warp*3] = p0; pred[warp*3+1] = p1; pred[warp*3+2] = p2; }
    __syncthreads();
    if (tid == 0) {
        float l0 = b2[0], l1 = b2[1], l2 = b2[2];
        for (int w = 0; w < 12; w++) { l0 += pred[w*3]; l1 += pred[w*3+1]; l2 += pred[w*3+2]; }
        float mm = fmaxf(l0, fmaxf(l1, l2));
        float e0 = __expf(l0 - mm), e1 = __expf(l1 - mm), e2 = __expf(l2 - mm);
        float z = e0 + e1 + e2;
        g_alphas[b*3+0] = e0 / z; g_alphas[b*3+1] = e1 / z; g_alphas[b*3+2] = e2 / z;
    }
}

// ---- bf16-split tensor-core GEMM ----
__device__ __forceinline__ void gemm_bf_body(const unsigned* __restrict__ Xp,
                                             const unsigned* __restrict__ Wp,
                                             const float* __restrict__ bias,
                                             void* __restrict__ outp,
                                             float scale, int omode,
                                             int row0, int col0) {
    __shared__ __align__(16) __nv_bfloat16 Ah[128][40], Al[128][40];
    __shared__ __align__(16) __nv_bfloat16 Bh[32][136], Bl[32][136];
    int tid = threadIdx.x;
    int wid = tid >> 5, lane = tid & 31;
    int wm = wid & 1, wn = wid >> 1;

    float acc[4][4][4];
    #pragma unroll
    for (int i = 0; i < 4; i++)
        #pragma unroll
        for (int j = 0; j < 4; j++)
            #pragma unroll
            for (int c = 0; c < 4; c++) acc[i][j][c] = 0.f;

    unsigned aaddr_h[4], aaddr_l[4];
    #pragma unroll
    for (int mt = 0; mt < 4; mt++) {
        aaddr_h[mt] = (unsigned)__cvta_generic_to_shared(
            &Ah[wm * 64 + mt * 16 + (lane & 15)][(lane >> 4) << 3]);
        aaddr_l[mt] = (unsigned)__cvta_generic_to_shared(
            &Al[wm * 64 + mt * 16 + (lane & 15)][(lane >> 4) << 3]);
    }
    unsigned baddr_h[2], baddr_l[2];
    #pragma unroll
    for (int nb = 0; nb < 2; nb++) {
        int kr = (lane & 7) + (((lane >> 3) & 1) << 3);
        int nc = wn * 32 + nb * 16 + ((lane >> 4) << 3);
        baddr_h[nb] = (unsigned)__cvta_generic_to_shared(&Bh[kr][nc]);
        baddr_l[nb] = (unsigned)__cvta_generic_to_shared(&Bl[kr][nc]);
    }

    for (int kt = 0; kt < 768; kt += 32) {
        __syncthreads();
        #pragma unroll
        for (int i = 0; i < 4; i++) {
            int e = tid + i * 256;
            int r = e >> 3, k0 = (e & 7) * 4;
            uint4 x = *(const uint4*)&Xp[(size_t)(row0 + r) * 768 + kt + k0];
            *(unsigned*)&Ah[r][k0]     = __byte_perm(x.x, x.y, 0x5410);
            *(unsigned*)&Al[r][k0]     = __byte_perm(x.x, x.y, 0x7632);
            *(unsigned*)&Ah[r][k0 + 2] = __byte_perm(x.z, x.w, 0x5410);
            *(unsigned*)&Al[r][k0 + 2] = __byte_perm(x.z, x.w, 0x7632);
        }
        #pragma unroll
        for (int i = 0; i < 4; i++) {
            int e = tid + i * 256;
            int kk = e >> 5, n0 = (e & 31) * 4;
            uint4 x = *(const uint4*)&Wp[(size_t)(kt + kk) * 768 + col0 + n0];
            *(unsigned*)&Bh[kk][n0]     = __byte_perm(x.x, x.y, 0x5410);
            *(unsigned*)&Bl[kk][n0]     = __byte_perm(x.x, x.y, 0x7632);
            *(unsigned*)&Bh[kk][n0 + 2] = __byte_perm(x.z, x.w, 0x5410);
            *(unsigned*)&Bl[kk][n0 + 2] = __byte_perm(x.z, x.w, 0x7632);
        }
        __syncthreads();
        #pragma unroll
        for (int ks = 0; ks < 2; ks++) {
            unsigned koff = ks * 32;
            unsigned ah[4][4], al[4][4], bh[2][4], bl[2][4];
            #pragma unroll
            for (int mt = 0; mt < 4; mt++) {
                LDSM4(ah[mt], aaddr_h[mt] + koff);
                LDSM4(al[mt], aaddr_l[mt] + koff);
            }
            #pragma unroll
            for (int nb = 0; nb < 2; nb++) {
                LDSM4T(bh[nb], baddr_h[nb] + ks * 16 * 272);
                LDSM4T(bl[nb], baddr_l[nb] + ks * 16 * 272);
            }
            #pragma unroll
            for (int mt = 0; mt < 4; mt++)
                #pragma unroll
                for (int nt = 0; nt < 4; nt++) {
                    unsigned bh0 = bh[nt >> 1][(nt & 1) * 2];
                    unsigned bh1 = bh[nt >> 1][(nt & 1) * 2 + 1];
                    unsigned bl0 = bl[nt >> 1][(nt & 1) * 2];
                    unsigned bl1 = bl[nt >> 1][(nt & 1) * 2 + 1];
                    MMABF(acc[mt][nt], ah[mt], bh0, bh1);
                    MMABF(acc[mt][nt], ah[mt], bl0, bl1);
                    MMABF(acc[mt][nt], al[mt], bh0, bh1);
                }
        }
    }

    int rbase = row0 + wm * 64, cbase = col0 + wn * 32;
    #pragma unroll
    for (int mt = 0; mt < 4; mt++) {
        #pragma unroll
        for (int nt = 0; nt < 4; nt++) {
            int gj = cbase + nt * 8 + (lane & 3) * 2;
            float b0 = __ldg(&bias[gj]), b1 = __ldg(&bias[gj + 1]);
            int r_lo = rbase + mt * 16 + (lane >> 2);
            int r_hi = r_lo + 8;
            float c00 = (acc[mt][nt][0] + b0) * scale;
            float c01 = (acc[mt][nt][1] + b1) * scale;
            float c10 = (acc[mt][nt][2] + b0) * scale;
            float c11 = (acc[mt][nt][3] + b1) * scale;
            if (omode == 1) {
                unsigned* out = (unsigned*)outp;
                int bb0 = r_lo >> 9, n0 = r_lo & 511;
                int h = gj >> 6, d = gj & 63;
                *(uint2*)&out[(((size_t)bb0 * HEADS + h) * SEQ + n0) * DK + d] =
                    make_uint2(packbf(c00), packbf(c01));
                int bb1 = r_hi >> 9, n1 = r_hi & 511;
                *(uint2*)&out[(((size_t)bb1 * HEADS + h) * SEQ + n1) * DK + d] =
                    make_uint2(packbf(c10), packbf(c11));
            } else {
                float* out = (float*)outp;
                *(float2*)&out[(size_t)r_lo * 768 + gj] = make_float2(c00, c01);
                *(float2*)&out[(size_t)r_hi * 768 + gj] = make_float2(c10, c11);
            }
        }
    }
}

__global__ __launch_bounds__(256) void gemm_qkv_bf(const float* __restrict__ bq,
                                                   const float* __restrict__ bk,
                                                   const float* __restrict__ bv) {
    int z = blockIdx.z;
    const unsigned* Xp; const unsigned* Wp; const float* bias; unsigned* out; float scale;
    if (z == 0)      { Xp = g_qbf; Wp = g_wbf;          bias = bq; out = g_qh; scale = 0.125f; }
    else if (z == 1) { Xp = g_kbf; Wp = g_wbf + K2;     bias = bk; out = g_kh; scale = 1.f; }
    else             { Xp = g_vbf; Wp = g_wbf + 2 * K2; bias = bv; out = g_vh; scale = 1.f; }
    gemm_bf_body(Xp, Wp, bias, out, scale, 1, blockIdx.y * 128, blockIdx.x * 128);
}

__global__ __launch_bounds__(256) void gemm_out_bf(const float* __restrict__ bias,
                                                   float* __restrict__ out) {
    gemm_bf_body(g_abf, g_wbf + 3 * K2, bias, out, 1.f, 0,
                 blockIdx.y * 128, blockIdx.x * 128);
}

// ---- fused attention, RT=32, 2 CTAs/SM ----
#define RT 32
#define SPITCH 516
#define QP 72
#define KP 72
#define AP 72
// smem byte offsets
#define OFF_S   0
#define OFF_QH  66048
#define OFF_QL  70656
#define OFF_W   75264
#define ATTN_SMEM 102912

__global__ __launch_bounds__(256, 2) void attn_kernel() {
    extern __shared__ char smc[];
    float* S = (float*)(smc + OFF_S);                       // 32 x 516 fp32
    __nv_bfloat16* Qh = (__nv_bfloat16*)(smc + OFF_QH);     // 32 x 72
    __nv_bfloat16* Ql = (__nv_bfloat16*)(smc + OFF_QL);
    __nv_bfloat16* Kh = (__nv_bfloat16*)(smc + OFF_W);      // 64 x 72 (phase 1)
    __nv_bfloat16* Kl = (__nv_bfloat16*)(smc + OFF_W + 9216);
    __nv_bfloat16* Ah = (__nv_bfloat16*)(smc + OFF_W);      // 32 x 72 (phase 3)
    __nv_bfloat16* Al = (__nv_bfloat16*)(smc + OFF_W + 4608);
    __nv_bfloat16* Vh = (__nv_bfloat16*)(smc + OFF_W + 9216);   // 64 x 72
    __nv_bfloat16* Vl = (__nv_bfloat16*)(smc + OFF_W + 18432);

    int rt = blockIdx.x, h = blockIdx.y, b = blockIdx.z;
    int tid = threadIdx.x;
    int wid = tid >> 5, lane = tid & 31;
    int wm = wid & 1, wn = wid >> 1;    // 2 x 4 warp grid

    const unsigned* Qg = g_qh + (((size_t)(b * HEADS + h)) * SEQ + rt * RT) * DK;
    const unsigned* Kg = g_kh + ((size_t)(b * HEADS + h)) * SEQ * DK;
    const unsigned* Vg = g_vh + ((size_t)(b * HEADS + h)) * SEQ * DK;

    // load Q (32x64 packed) -> Qh/Ql
    #pragma unroll
    for (int i = 0; i < 4; i++) {
        int idx = tid + i * 256;
        int r = idx >> 5, c2 = (idx & 31) * 2;
        uint2 u = *(const uint2*)&Qg[r * DK + c2];
        *(unsigned*)&Qh[r * QP + c2] = __byte_perm(u.x, u.y, 0x5410);
        *(unsigned*)&Ql[r * QP + c2] = __byte_perm(u.x, u.y, 0x7632);
    }

    // ldmatrix addresses
    unsigned qah = (unsigned)__cvta_generic_to_shared(
        &Qh[(wm * 16 + (lane & 15)) * QP + ((lane >> 4) << 3)]);
    unsigned qal = (unsigned)__cvta_generic_to_shared(
        &Ql[(wm * 16 + (lane & 15)) * QP + ((lane >> 4) << 3)]);
    unsigned kah = (unsigned)__cvta_generic_to_shared(
        &Kh[(wn * 16 + (lane & 15)) * KP + ((lane >> 4) << 3)]);
    unsigned kal = (unsigned)__cvta_generic_to_shared(
        &Kl[(wn * 16 + (lane & 15)) * KP + ((lane >> 4) << 3)]);

    // ---- phase 1: S[32][512] = Q K^T, 8 chunks of 64 cols ----
    for (int ch = 0; ch < 8; ch++) {
        __syncthreads();
        #pragma unroll
        for (int i = 0; i < 8; i++) {
            int idx = tid + i * 256;
            int r = idx >> 5, c2 = (idx & 31) * 2;
            uint2 u = *(const uint2*)&Kg[(ch * 64 + r) * DK + c2];
            *(unsigned*)&Kh[r * KP + c2] = __byte_perm(u.x, u.y, 0x5410);
            *(unsigned*)&Kl[r * KP + c2] = __byte_perm(u.x, u.y, 0x7632);
        }
        __syncthreads();
        float acc1[2][4];
        #pragma unroll
        for (int j = 0; j < 2; j++)
            #pragma unroll
            for (int c = 0; c < 4; c++) acc1[j][c] = 0.f;
        #pragma unroll
        for (int kc = 0; kc < 4; kc++) {
            unsigned koff = kc * 32;
            unsigned ah[4], al[4], bh[4], bl[4];
            LDSM4(ah, qah + koff);
            LDSM4(al, qal + koff);
            LDSM4(bh, kah + koff);
            LDSM4(bl, kal + koff);
            #pragma unroll
            for (int nt = 0; nt < 2; nt++) {
                unsigned b0h = bh[nt], b1h = bh[nt + 2];
                unsigned b0l = bl[nt], b1l = bl[nt + 2];
                MMABF(acc1[nt], ah, b0h, b1h);
                MMABF(acc1[nt], ah, b0l, b1l);
                MMABF(acc1[nt], al, b0h, b1h);
            }
        }
        #pragma unroll
        for (int nt = 0; nt < 2; nt++) {
            int r = wm * 16 + (lane >> 2);
            int c = ch * 64 + wn * 16 + nt * 8 + (lane & 3) * 2;
            *(float2*)&S[r * SPITCH + c] = make_float2(acc1[nt][0], acc1[nt][1]);
            *(float2*)&S[(r + 8) * SPITCH + c] = make_float2(acc1[nt][2], acc1[nt][3]);
        }
    }
    __syncthreads();

    // ---- phase 2: masked softmax algebra ----
    float wa0g = __ldg(&g_alphas[b*3+0]);
    float wa1g = __ldg(&g_alphas[b*3+1]);
    float wa2g = __ldg(&g_alphas[b*3+2]);
    for (int r = wid; r < RT; r += 8) {
        float* Sr = S + r * SPITCH;
        int n = rt * RT + r;
        const unsigned* p0 = g_packed + ((size_t)(0*BATCH + b) * SEQ + n) * 16;
        const unsigned* p1 = g_packed + ((size_t)(1*BATCH + b) * SEQ + n) * 16;
        const unsigned* p2 = g_packed + ((size_t)(2*BATCH + b) * SEQ + n) * 16;

        float mx = -1e30f;
        #pragma unroll
        for (int it = 0; it < 16; it++) mx = fmaxf(mx, Sr[it * 32 + lane]);
        #pragma unroll
        for (int o = 16; o; o >>= 1) mx = fmaxf(mx, __shfl_xor_sync(0xffffffffu, mx, o));

        float z0 = 0.f, z1 = 0.f, z2 = 0.f;
        #pragma unroll
        for (int it = 0; it < 16; it++) {
            int c = it * 32 + lane;
            float e = __expf(Sr[c] - mx);
            Sr[c] = e;
            unsigned w0 = __ldg(p0 + it), w1 = __ldg(p1 + it), w2 = __ldg(p2 + it);
            if (!((w0 >> lane) & 1)) z0 += e;
            if (!((w1 >> lane) & 1)) z1 += e;
            if (!((w2 >> lane) & 1)) z2 += e;
        }
        #pragma unroll
        for (int o = 16; o; o >>= 1) {
            z0 += __shfl_xor_sync(0xffffffffu, z0, o);
            z1 += __shfl_xor_sync(0xffffffffu, z1, o);
            z2 += __shfl_xor_sync(0xffffffffu, z2, o);
        }
        float wa0 = wa0g / z0, wa1 = wa1g / z1, wa2 = wa2g / z2;
        #pragma unroll
        for (int it = 0; it < 16; it++) {
            int c = it * 32 + lane;
            unsigned w0 = __ldg(p0 + it), w1 = __ldg(p1 + it), w2 = __ldg(p2 + it);
            float coef = (((w0 >> lane) & 1) ? 0.f : wa0)
                       + (((w1 >> lane) & 1) ? 0.f : wa1)
                       + (((w2 >> lane) & 1) ? 0.f : wa2);
            Sr[c] *= coef;
        }
    }

    // ---- phase 3: O[32][64] = A V, 8 chunks of 64 k-rows ----
    float acc3[2][4];
    #pragma unroll
    for (int j = 0; j < 2; j++)
        #pragma unroll
        for (int c = 0; c < 4; c++) acc3[j][c] = 0.f;

    unsigned aah = (unsigned)__cvta_generic_to_shared(
        &Ah[(wm * 16 + (lane & 15)) * AP + ((lane >> 4) << 3)]);
    unsigned aal = (unsigned)__cvta_generic_to_shared(
        &Al[(wm * 16 + (lane & 15)) * AP + ((lane >> 4) << 3)]);
    int vkr = (lane & 7) + (((lane >> 3) & 1) << 3);
    int vnc = wn * 16 + ((lane >> 4) << 3);
    unsigned vah = (unsigned)__cvta_generic_to_shared(&Vh[vkr * KP + vnc]);
    unsigned val = (unsigned)__cvta_generic_to_shared(&Vl[vkr * KP + vnc]);

    for (int ch = 0; ch < 8; ch++) {
        __syncthreads();
        // convert A chunk (32x64 fp32) -> split bf16
        #pragma unroll
        for (int i = 0; i < 4; i++) {
            int idx = tid + i * 256;
            int r = idx >> 5, c2 = (idx & 31) * 2;
            float2 v2 = *(const float2*)&S[r * SPITCH + ch * 64 + c2];
            unsigned pa = packbf(v2.x), pb = packbf(v2.y);
            *(unsigned*)&Ah[r * AP + c2] = __byte_perm(pa, pb, 0x5410);
            *(unsigned*)&Al[r * AP + c2] = __byte_perm(pa, pb, 0x7632);
        }
        // load V chunk (64x64 packed)
        #pragma unroll
        for (int i = 0; i < 8; i++) {
            int idx = tid + i * 256;
            int r = idx >> 5, c2 = (idx & 31) * 2;
            uint2 u = *(const uint2*)&Vg[(ch * 64 + r) * DK + c2];
            *(unsigned*)&Vh[r * KP + c2] = __byte_perm(u.x, u.y, 0x5410);
            *(unsigned*)&Vl[r * KP + c2] = __byte_perm(u.x, u.y, 0x7632);
        }
        __syncthreads();
        #pragma unroll
        for (int kc = 0; kc < 4; kc++) {
            unsigned koff = kc * 32;
            unsigned voff = kc * 16 * (KP * 2);
            unsigned ah[4], al[4], bh[4], bl[4];
            LDSM4(ah, aah + koff);
            LDSM4(al, aal + koff);
            LDSM4T(bh, vah + voff);
            LDSM4T(bl, val + voff);
            #pragma unroll
            for (int nt = 0; nt < 2; nt++) {
                unsigned b0h = bh[nt * 2], b1h = bh[nt * 2 + 1];
                unsigned b0l = bl[nt * 2], b1l = bl[nt * 2 + 1];
                MMABF(acc3[nt], ah, b0h, b1h);
                MMABF(acc3[nt], ah, b0l, b1l);
                MMABF(acc3[nt], al, b0h, b1h);
            }
        }
    }

    // epilogue: pack to g_abf [b*512+n][h*64+d]
    #pragma unroll
    for (int nt = 0; nt < 2; nt++) {
        int r = wm * 16 + (lane >> 2);
        int c = wn * 16 + nt * 8 + (lane & 3) * 2;
        size_t off0 = (size_t)(b * SEQ + rt * RT + r) * HIDDEN + h * 64 + c;
        size_t off1 = (size_t)(b * SEQ + rt * RT + r + 8) * HIDDEN + h * 64 + c;
        *(uint2*)&g_abf[off0] = make_uint2(packbf(acc3[nt][0]), packbf(acc3[nt][1]));
        *(uint2*)&g_abf[off1] = make_uint2(packbf(acc3[nt][2]), packbf(acc3[nt][3]));
    }
}

// ---- launch ----
extern "C" void kernel_launch(void* const* d_in, const int* in_sizes, int n_in,
                              void* d_out, int out_size) {
    const float* v = (const float*)d_in[0];
    const float* k = (const float*)d_in[1];
    const float* q = (const float*)d_in[2];
    const void*  masks = d_in[3];
    const float* Wv = (const float*)d_in[6];
    const float* bv = (const float*)d_in[7];
    const float* Wk = (const float*)d_in[8];
    const float* bk = (const float*)d_in[9];
    const float* Wq = (const float*)d_in[10];
    const float* bq = (const float*)d_in[11];
    const float* Wm = (const float*)d_in[12];
    const float* bm = (const float*)d_in[13];
    const float* pool_w = (const float*)d_in[14];
    const float* pool_b = (const float*)d_in[15];
    const float* w1 = (const float*)d_in[16];
    const float* w2 = (const float*)d_in[17];
    const float* b2 = (const float*)d_in[18];
    float* out = (float*)d_out;

    static cudaStream_t s1 = 0, s2 = 0;
    static cudaEvent_t evR = 0, ev1 = 0, ev2 = 0;
    if (!s1) {
        cudaStreamCreateWithFlags(&s1, cudaStreamNonBlocking);
        cudaStreamCreateWithFlags(&s2, cudaStreamNonBlocking);
        cudaEventCreateWithFlags(&evR, cudaEventDisableTiming);
        cudaEventCreateWithFlags(&ev1, cudaEventDisableTiming);
        cudaEventCreateWithFlags(&ev2, cudaEventDisableTiming);
        cudaFuncSetAttribute(attn_kernel, cudaFuncAttributeMaxDynamicSharedMemorySize, ATTN_SMEM);
    }

    cudaEventRecord(evR, 0);
    cudaStreamWaitEvent(s1, evR, 0);
    cudaStreamWaitEvent(s2, evR, 0);

    // s1: routing branch
    route_pool<<<BATCH, 256, 0, s1>>>(v, pool_w, pool_b);
    route_mlp<<<BATCH, 384, 0, s1>>>(w1, w2, b2);
    cudaEventRecord(ev1, s1);

    // s2: mask branch + weight conversion (independent of main chain)
    detect_mask_mode<<<1, 256, 0, s2>>>((const unsigned*)masks);
    pack_masks<<<ORDERS * BATCH * SEQ / 8, 256, 0, s2>>>(masks);
    conv_w<<<dim3(K2 / 1024, 4), 256, 0, s2>>>(Wq, Wk, Wv, Wm);
    cudaEventRecord(ev2, s2);

    // main: input conversion, then QKV (needs conv_w from s2)
    conv_x<<<dim3(BATCH * SEQ * HIDDEN / 1024, 3), 256>>>(q, k, v);
    cudaStreamWaitEvent(0, ev2, 0);

    dim3 gq(HIDDEN / 128, (BATCH * SEQ) / 128, 3);
    gemm_qkv_bf<<<gq, 256>>>(bq, bk, bv);

    cudaStreamWaitEvent(0, ev1, 0);

    attn_kernel<<<dim3(SEQ / RT, HEADS, BATCH), 256, ATTN_SMEM>>>();

    dim3 gg(HIDDEN / 128, (BATCH * SEQ) / 128);
    gemm_out_bf<<<gg, 256>>>(bm, out);
}

// round 12
// speedup vs baseline: 3.5972x; 1.1148x over previous
#include <cuda_runtime.h>
#include <cuda_bf16.h>
#include <math.h>

#define HIDDEN 768
#define HEADS  12
#define DK     64
#define BATCH  8
#define SEQ    512
#define ORDERS 3
#define NEGV   -1e9f
#define K2     (768 * 768)
#define NQKV   (BATCH * HEADS * SEQ * DK)

// q/k/v stored as SPLIT PLANES: hi (bf16 of x) and lo (bf16 of x - hi)
__device__ __nv_bfloat16 g_qhH[NQKV], g_qhL[NQKV];
__device__ __nv_bfloat16 g_khH[NQKV], g_khL[NQKV];
__device__ __nv_bfloat16 g_vhH[NQKV], g_vhL[NQKV];
__device__ float g_pooled[BATCH * HIDDEN];
__device__ float g_alphas[BATCH * ORDERS];
__device__ int   g_mask_mode;
__device__ unsigned g_packed[ORDERS * BATCH * SEQ * 16];
__device__ unsigned g_abf[BATCH * SEQ * HIDDEN];   // attn out, packed (lo<<16|hi)
__device__ unsigned g_wbf[4 * K2];                 // weights, packed (lo<<16|hi)

__device__ __forceinline__ unsigned packbf(float x) {
    __nv_bfloat16 h = __float2bfloat16_rn(x);
    float hf = __bfloat162float(h);
    __nv_bfloat16 l = __float2bfloat16_rn(x - hf);
    return ((unsigned)__bfloat16_as_ushort(l) << 16) | (unsigned)__bfloat16_as_ushort(h);
}

#define LDSM4(R, addr) \
    asm volatile("ldmatrix.sync.aligned.m8n8.x4.shared.b16 {%0,%1,%2,%3}, [%4];" \
        : "=r"((R)[0]), "=r"((R)[1]), "=r"((R)[2]), "=r"((R)[3]) : "r"(addr))
#define LDSM4T(R, addr) \
    asm volatile("ldmatrix.sync.aligned.m8n8.x4.trans.shared.b16 {%0,%1,%2,%3}, [%4];" \
        : "=r"((R)[0]), "=r"((R)[1]), "=r"((R)[2]), "=r"((R)[3]) : "r"(addr))
#define MMABF(C, A, B0, B1) \
    asm volatile("mma.sync.aligned.m16n8k16.row.col.f32.bf16.bf16.f32 " \
        "{%0,%1,%2,%3},{%4,%5,%6,%7},{%8,%9},{%0,%1,%2,%3};" \
        : "+f"((C)[0]), "+f"((C)[1]), "+f"((C)[2]), "+f"((C)[3]) \
        : "r"((A)[0]), "r"((A)[1]), "r"((A)[2]), "r"((A)[3]), "r"(B0), "r"(B1))
#define CPA16(s, g) \
    asm volatile("cp.async.cg.shared.global [%0], [%1], 16;" :: "r"(s), "l"(g) : "memory")
#define CPA_COMMIT() asm volatile("cp.async.commit_group;" ::: "memory")
#define CPA_WAIT1()  asm volatile("cp.async.wait_group 1;" ::: "memory")
#define CPA_WAIT0()  asm volatile("cp.async.wait_group 0;" ::: "memory")

// ---- weight conversion ----
__global__ __launch_bounds__(256) void conv_w(const float* __restrict__ wq,
                                              const float* __restrict__ wk,
                                              const float* __restrict__ wv,
                                              const float* __restrict__ wm) {
    int z = blockIdx.y;
    const float* src = (z == 0) ? wq : (z == 1) ? wk : (z == 2) ? wv : wm;
    unsigned* dst = g_wbf + (size_t)z * K2;
    size_t i = (size_t)blockIdx.x * 256 + threadIdx.x;
    float4 x = ((const float4*)src)[i];
    ((uint4*)dst)[i] = make_uint4(packbf(x.x), packbf(x.y), packbf(x.z), packbf(x.w));
}

// ---- mask detection + packing ----
__global__ void detect_mask_mode(const unsigned* __restrict__ m) {
    __shared__ int sflags;
    if (threadIdx.x == 0) sflags = 0;
    __syncthreads();
    int local = 0;
    for (int i = threadIdx.x; i < 16384; i += 256) {
        unsigned w = m[i];
        if (w == 0x3F800000u) local |= 1;
        else if (w != 0u && w != 1u) local |= 2;
    }
    if (local) atomicOr(&sflags, local);
    __syncthreads();
    if (threadIdx.x == 0)
        g_mask_mode = (sflags & 1) ? 2 : ((sflags & 2) ? 0 : 1);
}
__global__ __launch_bounds__(256) void pack_masks(const void* __restrict__ masks) {
    int mode = g_mask_mode;
    int warp = threadIdx.x >> 5, lane = threadIdx.x & 31;
    int row = blockIdx.x * 8 + warp;
    size_t base = (size_t)row * SEQ;
    #pragma unroll 4
    for (int w16 = 0; w16 < 16; w16++) {
        int c = w16 * 32 + lane;
        bool bit;
        if (mode == 1)      bit = ((const int*)masks)[base + c] != 0;
        else if (mode == 2) bit = ((const float*)masks)[base + c] != 0.f;
        else                bit = ((const unsigned char*)masks)[base + c] != 0;
        unsigned bal = __ballot_sync(0xffffffffu, bit);
        if (lane == 0) g_packed[row * 16 + w16] = bal;
    }
}

// ---- routing 1 ----
__global__ __launch_bounds__(256) void route_pool(const float* __restrict__ v,
                                                  const float* __restrict__ pool_w,
                                                  const float* __restrict__ pool_b) {
    int b = blockIdx.x;
    int tid = threadIdx.x, warp = tid >> 5, lane = tid & 31;
    __shared__ float sc[SEQ];
    __shared__ float red[8], red2[8];
    __shared__ float pw[HIDDEN];
    for (int d = tid; d < HIDDEN; d += 256) pw[d] = pool_w[d];
    __syncthreads();
    for (int n = warp; n < SEQ; n += 8) {
        const float* vp = v + ((size_t)b * SEQ + n) * HIDDEN;
        float dot = 0.f, asum = 0.f;
        #pragma unroll 4
        for (int d = lane; d < HIDDEN; d += 32) {
            float x = vp[d];
            dot += x * pw[d];
            asum += fabsf(x);
        }
        #pragma unroll
        for (int o = 16; o; o >>= 1) {
            dot  += __shfl_xor_sync(0xffffffffu, dot, o);
            asum += __shfl_xor_sync(0xffffffffu, asum, o);
        }
        if (lane == 0) sc[n] = (asum == 0.f) ? NEGV : (dot + pool_b[0]);
    }
    __syncthreads();
    float m = fmaxf(sc[tid], sc[tid + 256]);
    #pragma unroll
    for (int o = 16; o; o >>= 1) m = fmaxf(m, __shfl_xor_sync(0xffffffffu, m, o));
    if (lane == 0) red[warp] = m;
    __syncthreads();
    if (tid == 0) {
        float t = red[0];
        for (int i = 1; i < 8; i++) t = fmaxf(t, red[i]);
        red[0] = t;
    }
    __syncthreads();
    m = red[0];
    float e0 = __expf(sc[tid] - m), e1 = __expf(sc[tid + 256] - m);
    float s = e0 + e1;
    #pragma unroll
    for (int o = 16; o; o >>= 1) s += __shfl_xor_sync(0xffffffffu, s, o);
    if (lane == 0) red2[warp] = s;
    __syncthreads();
    if (tid == 0) {
        float t = 0.f;
        for (int i = 0; i < 8; i++) t += red2[i];
        red2[0] = t;
    }
    __syncthreads();
    float inv = 1.f / red2[0];
    sc[tid] = e0 * inv;
    sc[tid + 256] = e1 * inv;
    __syncthreads();
    float a0 = 0.f, a1 = 0.f, a2 = 0.f;
    #pragma unroll 4
    for (int n = 0; n < SEQ; n++) {
        float p = sc[n];
        const float* vp = v + ((size_t)b * SEQ + n) * HIDDEN;
        a0 += vp[tid] * p;
        a1 += vp[tid + 256] * p;
        a2 += vp[tid + 512] * p;
    }
    g_pooled[b * HIDDEN + tid]       = a0;
    g_pooled[b * HIDDEN + tid + 256] = a1;
    g_pooled[b * HIDDEN + tid + 512] = a2;
}

// ---- routing 2 ----
__global__ __launch_bounds__(384) void route_mlp(const float* __restrict__ w1,
                                                 const float* __restrict__ w2,
                                                 const float* __restrict__ b2) {
    int b = blockIdx.x, tid = threadIdx.x;
    __shared__ float pl[HIDDEN];
    __shared__ float pred[12 * 3];
    for (int d = tid; d < HIDDEN; d += 384) pl[d] = g_pooled[b * HIDDEN + d];
    __syncthreads();
    float acc = 0.f;
    #pragma unroll 16
    for (int k = 0; k < HIDDEN; k++) acc += pl[k] * __ldg(&w1[k * 384 + tid]);
    float hv = fmaxf(acc, 0.f);
    float p0 = hv * w2[tid * 3 + 0];
    float p1 = hv * w2[tid * 3 + 1];
    float p2 = hv * w2[tid * 3 + 2];
    #pragma unroll
    for (int o = 16; o; o >>= 1) {
        p0 += __shfl_xor_sync(0xffffffffu, p0, o);
        p1 += __shfl_xor_sync(0xffffffffu, p1, o);
        p2 += __shfl_xor_sync(0xffffffffu, p2, o);
    }
    int warp = tid >> 5;
    if ((tid & 31) == 0) { pred[warp*3] = p0; pred[warp*3+1] = p1; pred[warp*3+2] = p2; }
    __syncthreads();
    if (tid == 0) {
        float l0 = b2[0], l1 = b2[1], l2 = b2[2];
        for (int w = 0; w < 12; w++) { l0 += pred[w*3]; l1 += pred[w*3+1]; l2 += pred[w*3+2]; }
        float mm = fmaxf(l0, fmaxf(l1, l2));
        float e0 = __expf(l0 - mm), e1 = __expf(l1 - mm), e2 = __expf(l2 - mm);
        float z = e0 + e1 + e2;
        g_alphas[b*3+0] = e0 / z; g_alphas[b*3+1] = e1 / z; g_alphas[b*3+2] = e2 / z;
    }
}

// ---- bf16-split tensor-core GEMM ----
// xfmt 0: X packed (lo<<16|hi) unsigned; xfmt 1: X fp32 (converted inline)
// omode 0: fp32 out[i*768+j] (outA); omode 1: split planes outA=hi outB=lo, head layout
__device__ __forceinline__ void gemm_bf_body(const void* __restrict__ Xv, int xfmt,
                                             const unsigned* __restrict__ Wp,
                                             const float* __restrict__ bias,
                                             void* __restrict__ outA,
                                             void* __restrict__ outB,
                                             float scale, int omode,
                                             int row0, int col0) {
    __shared__ __align__(16) __nv_bfloat16 Ah[128][40], Al[128][40];
    __shared__ __align__(16) __nv_bfloat16 Bh[32][136], Bl[32][136];
    int tid = threadIdx.x;
    int wid = tid >> 5, lane = tid & 31;
    int wm = wid & 1, wn = wid >> 1;

    float acc[4][4][4];
    #pragma unroll
    for (int i = 0; i < 4; i++)
        #pragma unroll
        for (int j = 0; j < 4; j++)
            #pragma unroll
            for (int c = 0; c < 4; c++) acc[i][j][c] = 0.f;

    unsigned aaddr_h[4], aaddr_l[4];
    #pragma unroll
    for (int mt = 0; mt < 4; mt++) {
        aaddr_h[mt] = (unsigned)__cvta_generic_to_shared(
            &Ah[wm * 64 + mt * 16 + (lane & 15)][(lane >> 4) << 3]);
        aaddr_l[mt] = (unsigned)__cvta_generic_to_shared(
            &Al[wm * 64 + mt * 16 + (lane & 15)][(lane >> 4) << 3]);
    }
    unsigned baddr_h[2], baddr_l[2];
    #pragma unroll
    for (int nb = 0; nb < 2; nb++) {
        int kr = (lane & 7) + (((lane >> 3) & 1) << 3);
        int nc = wn * 32 + nb * 16 + ((lane >> 4) << 3);
        baddr_h[nb] = (unsigned)__cvta_generic_to_shared(&Bh[kr][nc]);
        baddr_l[nb] = (unsigned)__cvta_generic_to_shared(&Bl[kr][nc]);
    }

    for (int kt = 0; kt < 768; kt += 32) {
        __syncthreads();
        if (xfmt == 0) {
            const unsigned* Xp = (const unsigned*)Xv;
            #pragma unroll
            for (int i = 0; i < 4; i++) {
                int e = tid + i * 256;
                int r = e >> 3, k0 = (e & 7) * 4;
                uint4 x = *(const uint4*)&Xp[(size_t)(row0 + r) * 768 + kt + k0];
                *(unsigned*)&Ah[r][k0]     = __byte_perm(x.x, x.y, 0x5410);
                *(unsigned*)&Al[r][k0]     = __byte_perm(x.x, x.y, 0x7632);
                *(unsigned*)&Ah[r][k0 + 2] = __byte_perm(x.z, x.w, 0x5410);
                *(unsigned*)&Al[r][k0 + 2] = __byte_perm(x.z, x.w, 0x7632);
            }
        } else {
            const float* Xf = (const float*)Xv;
            #pragma unroll
            for (int i = 0; i < 4; i++) {
                int e = tid + i * 256;
                int r = e >> 3, k0 = (e & 7) * 4;
                float4 x = *(const float4*)&Xf[(size_t)(row0 + r) * 768 + kt + k0];
                unsigned p0 = packbf(x.x), p1 = packbf(x.y);
                unsigned p2 = packbf(x.z), p3 = packbf(x.w);
                *(unsigned*)&Ah[r][k0]     = __byte_perm(p0, p1, 0x5410);
                *(unsigned*)&Al[r][k0]     = __byte_perm(p0, p1, 0x7632);
                *(unsigned*)&Ah[r][k0 + 2] = __byte_perm(p2, p3, 0x5410);
                *(unsigned*)&Al[r][k0 + 2] = __byte_perm(p2, p3, 0x7632);
            }
        }
        #pragma unroll
        for (int i = 0; i < 4; i++) {
            int e = tid + i * 256;
            int kk = e >> 5, n0 = (e & 31) * 4;
            uint4 x = *(const uint4*)&Wp[(size_t)(kt + kk) * 768 + col0 + n0];
            *(unsigned*)&Bh[kk][n0]     = __byte_perm(x.x, x.y, 0x5410);
            *(unsigned*)&Bl[kk][n0]     = __byte_perm(x.x, x.y, 0x7632);
            *(unsigned*)&Bh[kk][n0 + 2] = __byte_perm(x.z, x.w, 0x5410);
            *(unsigned*)&Bl[kk][n0 + 2] = __byte_perm(x.z, x.w, 0x7632);
        }
        __syncthreads();
        #pragma unroll
        for (int ks = 0; ks < 2; ks++) {
            unsigned koff = ks * 32;
            unsigned ah[4][4], al[4][4], bh[2][4], bl[2][4];
            #pragma unroll
            for (int mt = 0; mt < 4; mt++) {
                LDSM4(ah[mt], aaddr_h[mt] + koff);
                LDSM4(al[mt], aaddr_l[mt] + koff);
            }
            #pragma unroll
            for (int nb = 0; nb < 2; nb++) {
                LDSM4T(bh[nb], baddr_h[nb] + ks * 16 * 272);
                LDSM4T(bl[nb], baddr_l[nb] + ks * 16 * 272);
            }
            #pragma unroll
            for (int mt = 0; mt < 4; mt++)
                #pragma unroll
                for (int nt = 0; nt < 4; nt++) {
                    unsigned bh0 = bh[nt >> 1][(nt & 1) * 2];
                    unsigned bh1 = bh[nt >> 1][(nt & 1) * 2 + 1];
                    unsigned bl0 = bl[nt >> 1][(nt & 1) * 2];
                    unsigned bl1 = bl[nt >> 1][(nt & 1) * 2 + 1];
                    MMABF(acc[mt][nt], ah[mt], bh0, bh1);
                    MMABF(acc[mt][nt], ah[mt], bl0, bl1);
                    MMABF(acc[mt][nt], al[mt], bh0, bh1);
                }
        }
    }

    int rbase = row0 + wm * 64, cbase = col0 + wn * 32;
    #pragma unroll
    for (int mt = 0; mt < 4; mt++) {
        #pragma unroll
        for (int nt = 0; nt < 4; nt++) {
            int gj = cbase + nt * 8 + (lane & 3) * 2;
            float b0 = __ldg(&bias[gj]), b1 = __ldg(&bias[gj + 1]);
            int r_lo = rbase + mt * 16 + (lane >> 2);
            int r_hi = r_lo + 8;
            float c00 = (acc[mt][nt][0] + b0) * scale;
            float c01 = (acc[mt][nt][1] + b1) * scale;
            float c10 = (acc[mt][nt][2] + b0) * scale;
            float c11 = (acc[mt][nt][3] + b1) * scale;
            if (omode == 1) {
                __nv_bfloat16* ohi = (__nv_bfloat16*)outA;
                __nv_bfloat16* olo = (__nv_bfloat16*)outB;
                unsigned p00 = packbf(c00), p01 = packbf(c01);
                unsigned p10 = packbf(c10), p11 = packbf(c11);
                int bb0 = r_lo >> 9, n0 = r_lo & 511;
                int h = gj >> 6, d = gj & 63;
                size_t o0 = (((size_t)bb0 * HEADS + h) * SEQ + n0) * DK + d;
                *(ushort2*)&ohi[o0] = make_ushort2((unsigned short)p00, (unsigned short)p01);
                *(ushort2*)&olo[o0] = make_ushort2((unsigned short)(p00 >> 16),
                                                   (unsigned short)(p01 >> 16));
                int bb1 = r_hi >> 9, n1 = r_hi & 511;
                size_t o1 = (((size_t)bb1 * HEADS + h) * SEQ + n1) * DK + d;
                *(ushort2*)&ohi[o1] = make_ushort2((unsigned short)p10, (unsigned short)p11);
                *(ushort2*)&olo[o1] = make_ushort2((unsigned short)(p10 >> 16),
                                                   (unsigned short)(p11 >> 16));
            } else {
                float* out = (float*)outA;
                *(float2*)&out[(size_t)r_lo * 768 + gj] = make_float2(c00, c01);
                *(float2*)&out[(size_t)r_hi * 768 + gj] = make_float2(c10, c11);
            }
        }
    }
}

__global__ __launch_bounds__(256) void gemm_qkv_bf(const float* __restrict__ q,
                                                   const float* __restrict__ k,
                                                   const float* __restrict__ v,
                                                   const float* __restrict__ bq,
                                                   const float* __restrict__ bk,
                                                   const float* __restrict__ bv) {
    int z = blockIdx.z;
    const float* X; const unsigned* Wp; const float* bias;
    __nv_bfloat16 *oh, *ol; float scale;
    if (z == 0)      { X = q; Wp = g_wbf;          bias = bq; oh = g_qhH; ol = g_qhL; scale = 0.125f; }
    else if (z == 1) { X = k; Wp = g_wbf + K2;     bias = bk; oh = g_khH; ol = g_khL; scale = 1.f; }
    else             { X = v; Wp = g_wbf + 2 * K2; bias = bv; oh = g_vhH; ol = g_vhL; scale = 1.f; }
    gemm_bf_body(X, 1, Wp, bias, oh, ol, scale, 1, blockIdx.y * 128, blockIdx.x * 128);
}

__global__ __launch_bounds__(256) void gemm_out_bf(const float* __restrict__ bias,
                                                   float* __restrict__ out) {
    gemm_bf_body(g_abf, 0, g_wbf + 3 * K2, bias, out, 0, 1.f, 0,
                 blockIdx.y * 128, blockIdx.x * 128);
}

// ---- fused attention: RT=32, 2 CTAs/SM, cp.async double-buffered fills ----
#define RT 32
#define SPITCH 516
// smem byte offsets: S 66048 | Q/A 9216 (hi 4608 + lo 4608) | buf0 18432 | buf1 18432
#define OFF_Q  66048
#define OFF_B0 75264
#define OFF_B1 93696
#define ATTN_SMEM 112128
#define PLB 9216      // plane size within a buffer (64 x 72 x 2B)

// fill one 64-row chunk (hi+lo planes) into buffer at dst (cp.async, 16B)
__device__ __forceinline__ void cpa_chunk64(unsigned dst,
                                            const __nv_bfloat16* __restrict__ hi,
                                            const __nv_bfloat16* __restrict__ lo,
                                            int tid) {
    #pragma unroll
    for (int i = 0; i < 2; i++) {
        int idx = tid + i * 256;
        int r = idx >> 3, sg = idx & 7;
        CPA16(dst + r * 144 + sg * 16, hi + r * 64 + sg * 8);
    }
    #pragma unroll
    for (int i = 0; i < 2; i++) {
        int idx = tid + i * 256;
        int r = idx >> 3, sg = idx & 7;
        CPA16(dst + PLB + r * 144 + sg * 16, lo + r * 64 + sg * 8);
    }
}

__global__ __launch_bounds__(256, 2) void attn_kernel() {
    extern __shared__ char smc[];
    float* S = (float*)smc;                                  // 32 x 516 fp32
    __nv_bfloat16* AhS = (__nv_bfloat16*)(smc + OFF_Q);      // 32 x 72 (A hi, phase 3)
    __nv_bfloat16* AlS = (__nv_bfloat16*)(smc + OFF_Q + 4608);
    unsigned sb = (unsigned)__cvta_generic_to_shared(smc);

    int rt = blockIdx.x, h = blockIdx.y, b = blockIdx.z;
    int tid = threadIdx.x;
    int wid = tid >> 5, lane = tid & 31;
    int wm = wid & 1, wn = wid >> 1;    // 2 x 4 warp grid

    size_t hoff = ((size_t)(b * HEADS + h)) * SEQ * DK;
    const __nv_bfloat16* QgH = g_qhH + hoff + rt * RT * DK;
    const __nv_bfloat16* QgL = g_qhL + hoff + rt * RT * DK;
    const __nv_bfloat16* KgH = g_khH + hoff;
    const __nv_bfloat16* KgL = g_khL + hoff;
    const __nv_bfloat16* VgH = g_vhH + hoff;
    const __nv_bfloat16* VgL = g_vhL + hoff;

    unsigned bufb0 = sb + OFF_B0, bufb1 = sb + OFF_B1;

    // ldmatrix addresses
    unsigned qrow = (wm * 16 + (lane & 15)) * 144 + ((lane >> 4) << 4);
    unsigned qah = sb + OFF_Q + qrow;            // Q (phase 1) / A (phase 3)
    unsigned qal = qah + 4608;
    unsigned krow = (wn * 16 + (lane & 15)) * 144 + ((lane >> 4) << 4);
    unsigned ka0h = bufb0 + krow, ka0l = ka0h + PLB;
    unsigned ka1h = bufb1 + krow, ka1l = ka1h + PLB;
    int vkr = (lane & 7) + (((lane >> 3) & 1) << 3);
    unsigned vrow = vkr * 144 + wn * 32 + ((lane >> 4) << 4);
    unsigned va0h = bufb0 + vrow, va0l = va0h + PLB;
    unsigned va1h = bufb1 + vrow, va1l = va1h + PLB;

    // prologue: Q + K0 (group), K1 (group)
    {
        int r = tid >> 3, sg = tid & 7;
        CPA16(sb + OFF_Q + r * 144 + sg * 16, QgH + r * 64 + sg * 8);
        CPA16(sb + OFF_Q + 4608 + r * 144 + sg * 16, QgL + r * 64 + sg * 8);
    }
    cpa_chunk64(bufb0, KgH, KgL, tid);
    CPA_COMMIT();
    cpa_chunk64(bufb1, KgH + 4096, KgL + 4096, tid);
    CPA_COMMIT();

    // ---- phase 1: S[32][512] = Q K^T, pipelined over 8 chunks of 64 cols ----
    unsigned qfh[4][4], qfl[4][4];
    #pragma unroll
    for (int ch = 0; ch < 8; ch++) {
        if (ch < 7) { CPA_WAIT1(); } else { CPA_WAIT0(); }
        __syncthreads();
        if (ch == 0) {
            #pragma unroll
            for (int kc = 0; kc < 4; kc++) {
                LDSM4(qfh[kc], qah + kc * 32);
                LDSM4(qfl[kc], qal + kc * 32);
            }
        }
        unsigned kh_ = (ch & 1) ? ka1h : ka0h;
        unsigned kl_ = (ch & 1) ? ka1l : ka0l;
        float acc1[2][4];
        #pragma unroll
        for (int j = 0; j < 2; j++)
            #pragma unroll
            for (int c = 0; c < 4; c++) acc1[j][c] = 0.f;
        #pragma unroll
        for (int kc = 0; kc < 4; kc++) {
            unsigned bh[4], bl[4];
            LDSM4(bh, kh_ + kc * 32);
            LDSM4(bl, kl_ + kc * 32);
            #pragma unroll
            for (int nt = 0; nt < 2; nt++) {
                MMABF(acc1[nt], qfh[kc], bh[nt], bh[nt + 2]);
                MMABF(acc1[nt], qfh[kc], bl[nt], bl[nt + 2]);
                MMABF(acc1[nt], qfl[kc], bh[nt], bh[nt + 2]);
            }
        }
        #pragma unroll
        for (int nt = 0; nt < 2; nt++) {
            int r = wm * 16 + (lane >> 2);
            int c = ch * 64 + wn * 16 + nt * 8 + (lane & 3) * 2;
            *(float2*)&S[r * SPITCH + c] = make_float2(acc1[nt][0], acc1[nt][1]);
            *(float2*)&S[(r + 8) * SPITCH + c] = make_float2(acc1[nt][2], acc1[nt][3]);
        }
        __syncthreads();
        if (ch < 6) {
            cpa_chunk64((ch & 1) ? bufb1 : bufb0,
                        KgH + (ch + 2) * 4096, KgL + (ch + 2) * 4096, tid);
            CPA_COMMIT();
        }
    }

    // prefetch V chunks 0,1 (land during phase 2)
    cpa_chunk64(bufb0, VgH, VgL, tid);
    CPA_COMMIT();
    cpa_chunk64(bufb1, VgH + 4096, VgL + 4096, tid);
    CPA_COMMIT();

    // ---- phase 2: masked softmax algebra ----
    float wa0g = __ldg(&g_alphas[b*3+0]);
    float wa1g = __ldg(&g_alphas[b*3+1]);
    float wa2g = __ldg(&g_alphas[b*3+2]);
    for (int r = wid; r < RT; r += 8) {
        float* Sr = S + r * SPITCH;
        int n = rt * RT + r;
        const unsigned* p0 = g_packed + ((size_t)(0*BATCH + b) * SEQ + n) * 16;
        const unsigned* p1 = g_packed + ((size_t)(1*BATCH + b) * SEQ + n) * 16;
        const unsigned* p2 = g_packed + ((size_t)(2*BATCH + b) * SEQ + n) * 16;

        float mx = -1e30f;
        #pragma unroll
        for (int it = 0; it < 16; it++) mx = fmaxf(mx, Sr[it * 32 + lane]);
        #pragma unroll
        for (int o = 16; o; o >>= 1) mx = fmaxf(mx, __shfl_xor_sync(0xffffffffu, mx, o));

        float z0 = 0.f, z1 = 0.f, z2 = 0.f;
        #pragma unroll
        for (int it = 0; it < 16; it++) {
            int c = it * 32 + lane;
            float e = __expf(Sr[c] - mx);
            Sr[c] = e;
            unsigned w0 = __ldg(p0 + it), w1 = __ldg(p1 + it), w2 = __ldg(p2 + it);
            if (!((w0 >> lane) & 1)) z0 += e;
            if (!((w1 >> lane) & 1)) z1 += e;
            if (!((w2 >> lane) & 1)) z2 += e;
        }
        #pragma unroll
        for (int o = 16; o; o >>= 1) {
            z0 += __shfl_xor_sync(0xffffffffu, z0, o);
            z1 += __shfl_xor_sync(0xffffffffu, z1, o);
            z2 += __shfl_xor_sync(0xffffffffu, z2, o);
        }
        float wa0 = wa0g / z0, wa1 = wa1g / z1, wa2 = wa2g / z2;
        #pragma unroll
        for (int it = 0; it < 16; it++) {
            int c = it * 32 + lane;
            unsigned w0 = __ldg(p0 + it), w1 = __ldg(p1 + it), w2 = __ldg(p2 + it);
            float coef = (((w0 >> lane) & 1) ? 0.f : wa0)
                       + (((w1 >> lane) & 1) ? 0.f : wa1)
                       + (((w2 >> lane) & 1) ? 0.f : wa2);
            Sr[c] *= coef;
        }
    }

    // ---- phase 3: O[32][64] = A V, pipelined over 8 chunks of 64 k-rows ----
    float acc3[2][4];
    #pragma unroll
    for (int j = 0; j < 2; j++)
        #pragma unroll
        for (int c = 0; c < 4; c++) acc3[j][c] = 0.f;

    #pragma unroll
    for (int ch = 0; ch < 8; ch++) {
        if (ch < 7) { CPA_WAIT1(); } else { CPA_WAIT0(); }
        __syncthreads();
        // convert A chunk (32x64 fp32 -> split bf16) into Q region
        #pragma unroll
        for (int i = 0; i < 4; i++) {
            int idx = tid + i * 256;
            int r = idx >> 5, c2 = (idx & 31) * 2;
            float2 v2 = *(const float2*)&S[r * SPITCH + ch * 64 + c2];
            unsigned pa = packbf(v2.x), pb = packbf(v2.y);
            *(unsigned*)&AhS[r * 72 + c2] = __byte_perm(pa, pb, 0x5410);
            *(unsigned*)&AlS[r * 72 + c2] = __byte_perm(pa, pb, 0x7632);
        }
        __syncthreads();
        unsigned vh_ = (ch & 1) ? va1h : va0h;
        unsigned vl_ = (ch & 1) ? va1l : va0l;
        #pragma unroll
        for (int kc = 0; kc < 4; kc++) {
            unsigned koff = kc * 32, voff = kc * 2304;   // 16 rows x 144B
            unsigned ah[4], al[4], bh[4], bl[4];
            LDSM4(ah, qah + koff);
            LDSM4(al, qal + koff);
            LDSM4T(bh, vh_ + voff);
            LDSM4T(bl, vl_ + voff);
            #pragma unroll
            for (int nt = 0; nt < 2; nt++) {
                MMABF(acc3[nt], ah, bh[nt * 2], bh[nt * 2 + 1]);
                MMABF(acc3[nt], ah, bl[nt * 2], bl[nt * 2 + 1]);
                MMABF(acc3[nt], al, bh[nt * 2], bh[nt * 2 + 1]);
            }
        }
        __syncthreads();
        if (ch < 6) {
            cpa_chunk64((ch & 1) ? bufb1 : bufb0,
                        VgH + (ch + 2) * 4096, VgL + (ch + 2) * 4096, tid);
            CPA_COMMIT();
        }
    }

    // epilogue: pack to g_abf [b*512+n][h*64+d]
    #pragma unroll
    for (int nt = 0; nt < 2; nt++) {
        int r = wm * 16 + (lane >> 2);
        int c = wn * 16 + nt * 8 + (lane & 3) * 2;
        size_t off0 = (size_t)(b * SEQ + rt * RT + r) * HIDDEN + h * 64 + c;
        size_t off1 = (size_t)(b * SEQ + rt * RT + r + 8) * HIDDEN + h * 64 + c;
        *(uint2*)&g_abf[off0] = make_uint2(packbf(acc3[nt][0]), packbf(acc3[nt][1]));
        *(uint2*)&g_abf[off1] = make_uint2(packbf(acc3[nt][2]), packbf(acc3[nt][3]));
    }
}

// ---- launch ----
extern "C" void kernel_launch(void* const* d_in, const int* in_sizes, int n_in,
                              void* d_out, int out_size) {
    const float* v = (const float*)d_in[0];
    const float* k = (const float*)d_in[1];
    const float* q = (const float*)d_in[2];
    const void*  masks = d_in[3];
    const float* Wv = (const float*)d_in[6];
    const float* bv = (const float*)d_in[7];
    const float* Wk = (const float*)d_in[8];
    const float* bk = (const float*)d_in[9];
    const float* Wq = (const float*)d_in[10];
    const float* bq = (const float*)d_in[11];
    const float* Wm = (const float*)d_in[12];
    const float* bm = (const float*)d_in[13];
    const float* pool_w = (const float*)d_in[14];
    const float* pool_b = (const float*)d_in[15];
    const float* w1 = (const float*)d_in[16];
    const float* w2 = (const float*)d_in[17];
    const float* b2 = (const float*)d_in[18];
    float* out = (float*)d_out;

    static cudaStream_t s1 = 0, s2 = 0;
    static cudaEvent_t evR = 0, ev1 = 0, ev2 = 0, ev3 = 0;
    if (!s1) {
        cudaStreamCreateWithFlags(&s1, cudaStreamNonBlocking);
        cudaStreamCreateWithFlags(&s2, cudaStreamNonBlocking);
        cudaEventCreateWithFlags(&evR, cudaEventDisableTiming);
        cudaEventCreateWithFlags(&ev1, cudaEventDisableTiming);
        cudaEventCreateWithFlags(&ev2, cudaEventDisableTiming);
        cudaEventCreateWithFlags(&ev3, cudaEventDisableTiming);
        cudaFuncSetAttribute(attn_kernel, cudaFuncAttributeMaxDynamicSharedMemorySize, ATTN_SMEM);
    }

    cudaEventRecord(evR, 0);
    cudaStreamWaitEvent(s1, evR, 0);
    cudaStreamWaitEvent(s2, evR, 0);

    // s1: routing branch
    route_pool<<<BATCH, 256, 0, s1>>>(v, pool_w, pool_b);
    route_mlp<<<BATCH, 384, 0, s1>>>(w1, w2, b2);
    cudaEventRecord(ev1, s1);

    // s2: weight conversion FIRST (gates QKV), then mask branch
    conv_w<<<dim3(K2 / 1024, 4), 256, 0, s2>>>(Wq, Wk, Wv, Wm);
    cudaEventRecord(ev2, s2);
    detect_mask_mode<<<1, 256, 0, s2>>>((const unsigned*)masks);
    pack_masks<<<ORDERS * BATCH * SEQ / 8, 256, 0, s2>>>(masks);
    cudaEventRecord(ev3, s2);

    // main: QKV projections (fp32 inputs, inline split) after weights ready
    cudaStreamWaitEvent(0, ev2, 0);
    dim3 gq(HIDDEN / 128, (BATCH * SEQ) / 128, 3);
    gemm_qkv_bf<<<gq, 256>>>(q, k, v, bq, bk, bv);

    cudaStreamWaitEvent(0, ev1, 0);
    cudaStreamWaitEvent(0, ev3, 0);

    attn_kernel<<<dim3(SEQ / RT, HEADS, BATCH), 256, ATTN_SMEM>>>();

    dim3 gg(HIDDEN / 128, (BATCH * SEQ) / 128);
    gemm_out_bf<<<gg, 256>>>(bm, out);
}